// round 5
// baseline (speedup 1.0000x reference)
#include <cuda_runtime.h>
#include <cuda_bf16.h>
#include <cstdint>

// Problem constants: N=100000, E=1600000, D=128, H=256, C=40
#define NN 100000
#define EE 1600000
#define DD 128
#define HH 256
#define CC 40

// ---------------- scratch (static device globals) ---------------------------
__device__ float g_rst[(size_t)NN * HH];
__device__ float g_t[(size_t)NN * HH];
__device__ float g_h[(size_t)NN * HH];
__device__ int   g_rowstart[NN + 1];
__device__ int   g_cursor[NN];
__device__ int   g_csr[EE];

// ---------------- CSR build ------------------------------------------------
__global__ void hist_kernel(const int* __restrict__ dst, int* __restrict__ cnt, int e) {
    int i = blockIdx.x * blockDim.x + threadIdx.x;
    if (i < e) atomicAdd(&cnt[dst[i]], 1);
}

__global__ void scan_kernel(int* __restrict__ cnt_cursor, int* __restrict__ row_start, int n) {
    __shared__ int wsum[32];
    __shared__ int carry;
    const int tid = threadIdx.x;
    const int lane = tid & 31;
    const int wid = tid >> 5;
    if (tid == 0) carry = 0;
    __syncthreads();
    for (int base = 0; base < n; base += 1024) {
        int i = base + tid;
        int v = (i < n) ? cnt_cursor[i] : 0;
        int x = v;
        #pragma unroll
        for (int o = 1; o < 32; o <<= 1) {
            int y = __shfl_up_sync(0xffffffffu, x, o);
            if (lane >= o) x += y;
        }
        if (lane == 31) wsum[wid] = x;
        __syncthreads();
        if (wid == 0) {
            int wv = wsum[lane];
            #pragma unroll
            for (int o = 1; o < 32; o <<= 1) {
                int y = __shfl_up_sync(0xffffffffu, wv, o);
                if (lane >= o) wv += y;
            }
            wsum[lane] = wv;
        }
        __syncthreads();
        int excl = x - v + (wid ? wsum[wid - 1] : 0) + carry;
        if (i < n) { row_start[i] = excl; cnt_cursor[i] = excl; }
        if (i == n - 1) row_start[n] = excl + v;
        __syncthreads();
        if (tid == 0) carry += wsum[31];
        __syncthreads();
    }
}

__global__ void fill_kernel(const int* __restrict__ src, const int* __restrict__ dst,
                            int* __restrict__ cursor, int* __restrict__ csr, int e) {
    int i = blockIdx.x * blockDim.x + threadIdx.x;
    if (i < e) {
        int p = atomicAdd(&cursor[dst[i]], 1);
        csr[p] = src[i];
    }
}

// ---------------- aggregation (gather, warp/node) ---------------------------
template <int DIM>
__global__ __launch_bounds__(256) void agg_kernel(
    const float4* __restrict__ h, const int* __restrict__ rs,
    const int* __restrict__ csr, const float* __restrict__ eps,
    float4* __restrict__ out, int n)
{
    int w = (blockIdx.x * 256 + threadIdx.x) >> 5;
    if (w >= n) return;
    int lane = threadIdx.x & 31;
    constexpr int V = DIM / 128;
    float s = 1.0f + *eps;
    size_t base = (size_t)w * (DIM / 4);
    float4 acc[V];
    #pragma unroll
    for (int j = 0; j < V; j++) {
        float4 v = h[base + lane + 32 * j];
        acc[j] = make_float4(v.x * s, v.y * s, v.z * s, v.w * s);
    }
    int e0 = rs[w], e1 = rs[w + 1];
    for (int e = e0; e < e1; e++) {
        size_t b2 = (size_t)csr[e] * (DIM / 4);
        #pragma unroll
        for (int j = 0; j < V; j++) {
            float4 v = h[b2 + lane + 32 * j];
            acc[j].x += v.x; acc[j].y += v.y; acc[j].z += v.z; acc[j].w += v.w;
        }
    }
    #pragma unroll
    for (int j = 0; j < V; j++) out[base + lane + 32 * j] = acc[j];
}

// ---------------- tensor-core GEMM (bf16 3-product split) -------------------
__device__ __forceinline__ void ldsm4(uint32_t* r, uint32_t addr) {
    asm volatile("ldmatrix.sync.aligned.m8n8.x4.shared.b16 {%0,%1,%2,%3}, [%4];\n"
        : "=r"(r[0]), "=r"(r[1]), "=r"(r[2]), "=r"(r[3]) : "r"(addr));
}
__device__ __forceinline__ void ldsm4t(uint32_t* r, uint32_t addr) {
    asm volatile("ldmatrix.sync.aligned.m8n8.x4.trans.shared.b16 {%0,%1,%2,%3}, [%4];\n"
        : "=r"(r[0]), "=r"(r[1]), "=r"(r[2]), "=r"(r[3]) : "r"(addr));
}
__device__ __forceinline__ void mma16816(float* c, const uint32_t* a, const uint32_t* b) {
    asm volatile("mma.sync.aligned.m16n8k16.row.col.f32.bf16.bf16.f32 "
        "{%0,%1,%2,%3}, {%4,%5,%6,%7}, {%8,%9}, {%0,%1,%2,%3};\n"
        : "+f"(c[0]), "+f"(c[1]), "+f"(c[2]), "+f"(c[3])
        : "r"(a[0]), "r"(a[1]), "r"(a[2]), "r"(a[3]), "r"(b[0]), "r"(b[1]));
}

union BF2U { __nv_bfloat162 b2; uint32_t u; };
__device__ __forceinline__ uint32_t packbf(__nv_bfloat16 a, __nv_bfloat16 b) {
    BF2U t; t.b2 = __halves2bfloat162(a, b); return t.u;
}
// Split float4 (4 consecutive k values) into hi/lo bf16, packed as uint2 each.
__device__ __forceinline__ void cvt_split(float4 v, uint2& hi, uint2& lo) {
    __nv_bfloat16 hx = __float2bfloat16_rn(v.x);
    __nv_bfloat16 hy = __float2bfloat16_rn(v.y);
    __nv_bfloat16 hz = __float2bfloat16_rn(v.z);
    __nv_bfloat16 hw = __float2bfloat16_rn(v.w);
    __nv_bfloat16 lx = __float2bfloat16_rn(v.x - __bfloat162float(hx));
    __nv_bfloat16 ly = __float2bfloat16_rn(v.y - __bfloat162float(hy));
    __nv_bfloat16 lz = __float2bfloat16_rn(v.z - __bfloat162float(hz));
    __nv_bfloat16 lw = __float2bfloat16_rn(v.w - __bfloat162float(hw));
    hi.x = packbf(hx, hy); hi.y = packbf(hz, hw);
    lo.x = packbf(lx, ly); lo.y = packbf(lz, lw);
}

// C[n,M] = act(A[n,K] @ B[K,M] (+bias)); K % 32 == 0, M % 4 == 0.
// BM=128, BN=128, BK=32; 8 warps, warp tile 32x64.
template <bool RELU, bool BIAS>
__global__ __launch_bounds__(256, 1) void gemm_tc(
    const float* __restrict__ A, const float* __restrict__ Bw,
    const float* __restrict__ bias, float* __restrict__ C,
    int n, int K, int M)
{
    constexpr int BM = 128, BN = 128, BK = 32;
    constexpr int SA = BK + 8;   // bf16 stride for A tiles  -> conflict-free ldmatrix
    constexpr int SB = BN + 8;   // bf16 stride for B tiles
    __shared__ __nv_bfloat16 AsH[BM * SA], AsL[BM * SA];
    __shared__ __nv_bfloat16 BsH[BK * SB], BsL[BK * SB];

    const int tid  = threadIdx.x;
    const int warp = tid >> 5, lane = tid & 31;
    const int wm = (warp & 3) * 32;       // warp M offset in tile
    const int wn = (warp >> 2) * 64;      // warp N offset in tile
    const int m0 = blockIdx.x * BM;
    const int n0 = blockIdx.y * BN;

    // global load mapping
    const int arow = tid >> 3;            // 0..31 (row within 32-row chunk)
    const int acol = (tid & 7) * 4;       // k offset, float4
    const int brow = tid >> 5;            // 0..7
    const int bcol = (tid & 31) * 4;      // col offset, float4

    float acc[2][8][4];
    #pragma unroll
    for (int i = 0; i < 2; i++)
        #pragma unroll
        for (int j = 0; j < 8; j++)
            #pragma unroll
            for (int q = 0; q < 4; q++) acc[i][j][q] = 0.f;

    uint2 aH[4], aL[4], bH[4], bL[4];     // register-staged next tile

    auto loadAB = [&](int k0) {
        #pragma unroll
        for (int r = 0; r < 4; r++) {
            int g = m0 + arow + r * 32;
            float4 v = make_float4(0.f, 0.f, 0.f, 0.f);
            if (g < n) v = *(const float4*)(A + (size_t)g * K + k0 + acol);
            cvt_split(v, aH[r], aL[r]);
        }
        #pragma unroll
        for (int r = 0; r < 4; r++) {
            int kk = k0 + brow + r * 8;
            int gm = n0 + bcol;
            float4 v = make_float4(0.f, 0.f, 0.f, 0.f);
            if (gm + 3 < M) v = *(const float4*)(Bw + (size_t)kk * M + gm);
            cvt_split(v, bH[r], bL[r]);
        }
    };
    auto storeAB = [&]() {
        #pragma unroll
        for (int r = 0; r < 4; r++) {
            int off = (arow + r * 32) * SA + acol;
            *(uint2*)(AsH + off) = aH[r];
            *(uint2*)(AsL + off) = aL[r];
        }
        #pragma unroll
        for (int r = 0; r < 4; r++) {
            int off = (brow + r * 8) * SB + bcol;
            *(uint2*)(BsH + off) = bH[r];
            *(uint2*)(BsL + off) = bL[r];
        }
    };

    loadAB(0);
    storeAB();
    __syncthreads();

    const uint32_t sAsH = (uint32_t)__cvta_generic_to_shared(AsH);
    const uint32_t sAsL = (uint32_t)__cvta_generic_to_shared(AsL);
    const uint32_t sBsH = (uint32_t)__cvta_generic_to_shared(BsH);
    const uint32_t sBsL = (uint32_t)__cvta_generic_to_shared(BsL);

    // per-lane ldmatrix offsets
    const int aLm = lane & 15, aLk = (lane >> 4) << 3;   // A: row, k-offset
    const int bLk = lane & 15, bLn = (lane >> 4) << 3;   // B: k-row, n-offset

    for (int k0 = 0; k0 < K; k0 += BK) {
        bool more = (k0 + BK) < K;
        if (more) loadAB(k0 + BK);   // global loads in flight during mma

        #pragma unroll
        for (int ks = 0; ks < BK; ks += 16) {
            uint32_t afH[2][4], afL[2][4], bfH[4][4], bfL[4][4];
            #pragma unroll
            for (int mt = 0; mt < 2; mt++) {
                uint32_t off = ((wm + mt * 16 + aLm) * SA + ks + aLk) * 2;
                ldsm4(afH[mt], sAsH + off);
                ldsm4(afL[mt], sAsL + off);
            }
            #pragma unroll
            for (int ng = 0; ng < 4; ng++) {
                uint32_t off = ((ks + bLk) * SB + wn + ng * 16 + bLn) * 2;
                ldsm4t(bfH[ng], sBsH + off);
                ldsm4t(bfL[ng], sBsL + off);
            }
            #pragma unroll
            for (int mt = 0; mt < 2; mt++)
                #pragma unroll
                for (int nb = 0; nb < 8; nb++) {
                    const uint32_t* bh = &bfH[nb >> 1][(nb & 1) * 2];
                    const uint32_t* bl = &bfL[nb >> 1][(nb & 1) * 2];
                    mma16816(acc[mt][nb], afH[mt], bh);   // hi*hi
                    mma16816(acc[mt][nb], afH[mt], bl);   // hi*lo
                    mma16816(acc[mt][nb], afL[mt], bh);   // lo*hi
                }
        }

        if (more) {
            __syncthreads();
            storeAB();
            __syncthreads();
        }
    }

    // epilogue: c0:(r,c) c1:(r,c+1) c2:(r+8,c) c3:(r+8,c+1)
    #pragma unroll
    for (int mt = 0; mt < 2; mt++)
        #pragma unroll
        for (int nb = 0; nb < 8; nb++) {
            int row = m0 + wm + mt * 16 + (lane >> 2);
            int col = n0 + wn + nb * 8 + (lane & 3) * 2;
            if (col >= M) continue;
            float v0 = acc[mt][nb][0], v1 = acc[mt][nb][1];
            float v2 = acc[mt][nb][2], v3 = acc[mt][nb][3];
            if (BIAS) {
                float b0 = bias[col], b1 = bias[col + 1];
                v0 += b0; v1 += b1; v2 += b0; v3 += b1;
            }
            if (RELU) {
                v0 = fmaxf(v0, 0.f); v1 = fmaxf(v1, 0.f);
                v2 = fmaxf(v2, 0.f); v3 = fmaxf(v3, 0.f);
            }
            if (row < n)
                *(float2*)(C + (size_t)row * M + col) = make_float2(v0, v1);
            if (row + 8 < n)
                *(float2*)(C + (size_t)(row + 8) * M + col) = make_float2(v2, v3);
        }
}

// ---------------- launch ----------------------------------------------------
extern "C" void kernel_launch(void* const* d_in, const int* in_sizes, int n_in,
                              void* d_out, int out_size) {
    const float* x    = (const float*)d_in[0];
    const int*   src  = (const int*)d_in[1];
    const int*   dst  = (const int*)d_in[2];
    const float* eps1 = (const float*)d_in[3];
    const float* w1a  = (const float*)d_in[4];
    const float* w1b  = (const float*)d_in[5];
    const float* eps2 = (const float*)d_in[6];
    const float* w2a  = (const float*)d_in[7];
    const float* w2b  = (const float*)d_in[8];
    const float* fcw  = (const float*)d_in[9];
    const float* fcb  = (const float*)d_in[10];
    float* out = (float*)d_out;

    const int n = in_sizes[0] / DD;   // 100000
    const int e = in_sizes[1];        // 1600000

    float *rst, *t, *h;
    int *rs, *cur, *csr;
    cudaGetSymbolAddress((void**)&rst, g_rst);
    cudaGetSymbolAddress((void**)&t,   g_t);
    cudaGetSymbolAddress((void**)&h,   g_h);
    cudaGetSymbolAddress((void**)&rs,  g_rowstart);
    cudaGetSymbolAddress((void**)&cur, g_cursor);
    cudaGetSymbolAddress((void**)&csr, g_csr);

    // CSR build (dst-grouped)
    cudaMemsetAsync(cur, 0, (size_t)n * sizeof(int));
    int eb = (e + 255) / 256;
    hist_kernel<<<eb, 256>>>(dst, cur, e);
    scan_kernel<<<1, 1024>>>(cur, rs, n);
    fill_kernel<<<eb, 256>>>(src, dst, cur, csr, e);

    const int aggBlocks = (n + 7) / 8;
    const int gm = (n + 127) / 128;
    dim3 gFull(gm, HH / 128);   // (782, 2)
    dim3 gFc(gm, 1);

    // Layer 1
    agg_kernel<DD><<<aggBlocks, 256>>>((const float4*)x, rs, csr, eps1, (float4*)rst, n);
    gemm_tc<true,  false><<<gFull, 256>>>(rst, w1a, nullptr, t, n, DD, HH);
    gemm_tc<true,  false><<<gFull, 256>>>(t,   w1b, nullptr, h, n, HH, HH);
    // Layer 2
    agg_kernel<HH><<<aggBlocks, 256>>>((const float4*)h, rs, csr, eps2, (float4*)rst, n);
    gemm_tc<true,  false><<<gFull, 256>>>(rst, w2a, nullptr, t, n, HH, HH);
    gemm_tc<true,  false><<<gFull, 256>>>(t,   w2b, nullptr, h, n, HH, HH);
    // Classifier
    gemm_tc<false, true ><<<gFc,   256>>>(h,   fcw, fcb,     out, n, HH, CC);
}

// round 7
// speedup vs baseline: 1.5659x; 1.5659x over previous
#include <cuda_runtime.h>
#include <cuda_bf16.h>
#include <cstdint>

// Problem constants: N=100000, E=1600000, D=128, H=256, C=40
#define NN 100000
#define EE 1600000
#define DD 128
#define HH 256
#define CC 40

typedef __nv_bfloat16 bf16;

// ---------------- scratch (static device globals) ---------------------------
// Split-bf16 interchange buffers (hi/lo planes)
__device__ bf16 g_aH[(size_t)NN * HH], g_aL[(size_t)NN * HH];   // rst
__device__ bf16 g_tH[(size_t)NN * HH], g_tL[(size_t)NN * HH];   // mid
__device__ bf16 g_hH[(size_t)NN * HH], g_hL[(size_t)NN * HH];   // layer out
#define W_TOT (32768 + 65536 + 65536 + 65536 + 10240)
__device__ bf16 g_wH[W_TOT], g_wL[W_TOT];
__device__ int  g_rowstart[NN + 1];
__device__ int  g_cursor[NN];
__device__ int  g_csr[EE];

// ---------------- CSR build ------------------------------------------------
__global__ void hist_kernel(const int* __restrict__ dst, int* __restrict__ cnt, int e) {
    int i = blockIdx.x * blockDim.x + threadIdx.x;
    if (i < e) atomicAdd(&cnt[dst[i]], 1);
}

__global__ void scan_kernel(int* __restrict__ cnt_cursor, int* __restrict__ row_start, int n) {
    __shared__ int wsum[32];
    __shared__ int carry;
    const int tid = threadIdx.x;
    const int lane = tid & 31;
    const int wid = tid >> 5;
    if (tid == 0) carry = 0;
    __syncthreads();
    for (int base = 0; base < n; base += 1024) {
        int i = base + tid;
        int v = (i < n) ? cnt_cursor[i] : 0;
        int x = v;
        #pragma unroll
        for (int o = 1; o < 32; o <<= 1) {
            int y = __shfl_up_sync(0xffffffffu, x, o);
            if (lane >= o) x += y;
        }
        if (lane == 31) wsum[wid] = x;
        __syncthreads();
        if (wid == 0) {
            int wv = wsum[lane];
            #pragma unroll
            for (int o = 1; o < 32; o <<= 1) {
                int y = __shfl_up_sync(0xffffffffu, wv, o);
                if (lane >= o) wv += y;
            }
            wsum[lane] = wv;
        }
        __syncthreads();
        int excl = x - v + (wid ? wsum[wid - 1] : 0) + carry;
        if (i < n) { row_start[i] = excl; cnt_cursor[i] = excl; }
        if (i == n - 1) row_start[n] = excl + v;
        __syncthreads();
        if (tid == 0) carry += wsum[31];
        __syncthreads();
    }
}

__global__ void fill_kernel(const int* __restrict__ src, const int* __restrict__ dst,
                            int* __restrict__ cursor, int* __restrict__ csr, int e) {
    int i = blockIdx.x * blockDim.x + threadIdx.x;
    if (i < e) {
        int p = atomicAdd(&cursor[dst[i]], 1);
        csr[p] = src[i];
    }
}

// ---------------- bf16 split helpers ----------------------------------------
union BF2U { __nv_bfloat162 b2; uint32_t u; };
__device__ __forceinline__ uint32_t packbf(bf16 a, bf16 b) {
    BF2U t; t.b2 = __halves2bfloat162(a, b); return t.u;
}
__device__ __forceinline__ void split_pair(float v0, float v1, uint32_t& hu, uint32_t& lu) {
    bf16 h0 = __float2bfloat16_rn(v0), h1 = __float2bfloat16_rn(v1);
    bf16 l0 = __float2bfloat16_rn(v0 - __bfloat162float(h0));
    bf16 l1 = __float2bfloat16_rn(v1 - __bfloat162float(h1));
    hu = packbf(h0, h1); lu = packbf(l0, l1);
}
__device__ __forceinline__ float2 unpk_bf2(uint32_t u) {
    BF2U t; t.u = u; return __bfloat1622float2(t.b2);
}

// Weight splitter: count % 4 == 0
__global__ void split_kernel(const float* __restrict__ src, bf16* __restrict__ dh,
                             bf16* __restrict__ dl, int cnt) {
    int i = blockIdx.x * blockDim.x + threadIdx.x;
    if (i * 4 < cnt) {
        float4 v = ((const float4*)src)[i];
        uint2 hi, lo;
        split_pair(v.x, v.y, hi.x, lo.x);
        split_pair(v.z, v.w, hi.y, lo.y);
        ((uint2*)dh)[i] = hi;
        ((uint2*)dl)[i] = lo;
    }
}

// ---------------- aggregation (gather, warp/node) ---------------------------
// agg1: fp32 input (x, D=128) -> split output
__global__ __launch_bounds__(256) void agg_f32(
    const float4* __restrict__ h, const int* __restrict__ rs,
    const int* __restrict__ csr, const float* __restrict__ eps,
    bf16* __restrict__ oH, bf16* __restrict__ oL, int n)
{
    int w = (blockIdx.x * 256 + threadIdx.x) >> 5;
    if (w >= n) return;
    int lane = threadIdx.x & 31;
    float s = 1.0f + *eps;
    float4 v = h[(size_t)w * 32 + lane];
    float a0 = v.x * s, a1 = v.y * s, a2 = v.z * s, a3 = v.w * s;
    int e0 = rs[w], e1 = rs[w + 1];
    for (int e = e0; e < e1; e++) {
        float4 u = h[(size_t)csr[e] * 32 + lane];
        a0 += u.x; a1 += u.y; a2 += u.z; a3 += u.w;
    }
    uint2 hi, lo;
    split_pair(a0, a1, hi.x, lo.x);
    split_pair(a2, a3, hi.y, lo.y);
    size_t oi = (size_t)w * 64 + lane * 2;   // u32 index (2 bf16 per u32)
    *(uint2*)((uint32_t*)oH + oi) = hi;
    *(uint2*)((uint32_t*)oL + oi) = lo;
}

// agg2: split input (D=256) -> split output
__global__ __launch_bounds__(256) void agg_split(
    const bf16* __restrict__ iH, const bf16* __restrict__ iL,
    const int* __restrict__ rs, const int* __restrict__ csr,
    const float* __restrict__ eps,
    bf16* __restrict__ oH, bf16* __restrict__ oL, int n)
{
    int w = (blockIdx.x * 256 + threadIdx.x) >> 5;
    if (w >= n) return;
    int lane = threadIdx.x & 31;
    float s = 1.0f + *eps;
    float acc[8];
    {
        uint4 hv = ((const uint4*)(iH + (size_t)w * 256))[lane];
        uint4 lv = ((const uint4*)(iL + (size_t)w * 256))[lane];
        const uint32_t* hp = (const uint32_t*)&hv;
        const uint32_t* lp = (const uint32_t*)&lv;
        #pragma unroll
        for (int j = 0; j < 4; j++) {
            float2 fh = unpk_bf2(hp[j]), fl = unpk_bf2(lp[j]);
            acc[2 * j]     = (fh.x + fl.x) * s;
            acc[2 * j + 1] = (fh.y + fl.y) * s;
        }
    }
    int e0 = rs[w], e1 = rs[w + 1];
    for (int e = e0; e < e1; e++) {
        size_t b = (size_t)csr[e] * 256;
        uint4 hv = ((const uint4*)(iH + b))[lane];
        uint4 lv = ((const uint4*)(iL + b))[lane];
        const uint32_t* hp = (const uint32_t*)&hv;
        const uint32_t* lp = (const uint32_t*)&lv;
        #pragma unroll
        for (int j = 0; j < 4; j++) {
            float2 fh = unpk_bf2(hp[j]), fl = unpk_bf2(lp[j]);
            acc[2 * j]     += fh.x + fl.x;
            acc[2 * j + 1] += fh.y + fl.y;
        }
    }
    uint4 hi, lo;
    split_pair(acc[0], acc[1], hi.x, lo.x);
    split_pair(acc[2], acc[3], hi.y, lo.y);
    split_pair(acc[4], acc[5], hi.z, lo.z);
    split_pair(acc[6], acc[7], hi.w, lo.w);
    size_t oi = (size_t)w * 128 + lane * 4;
    *(uint4*)((uint32_t*)oH + oi) = hi;
    *(uint4*)((uint32_t*)oL + oi) = lo;
}

// ---------------- mma.sync helpers ------------------------------------------
__device__ __forceinline__ void ldsm4(uint32_t* r, uint32_t addr) {
    asm volatile("ldmatrix.sync.aligned.m8n8.x4.shared.b16 {%0,%1,%2,%3}, [%4];\n"
        : "=r"(r[0]), "=r"(r[1]), "=r"(r[2]), "=r"(r[3]) : "r"(addr));
}
__device__ __forceinline__ void ldsm4t(uint32_t* r, uint32_t addr) {
    asm volatile("ldmatrix.sync.aligned.m8n8.x4.trans.shared.b16 {%0,%1,%2,%3}, [%4];\n"
        : "=r"(r[0]), "=r"(r[1]), "=r"(r[2]), "=r"(r[3]) : "r"(addr));
}
__device__ __forceinline__ void mma16816(float* c, const uint32_t* a, const uint32_t* b) {
    asm volatile("mma.sync.aligned.m16n8k16.row.col.f32.bf16.bf16.f32 "
        "{%0,%1,%2,%3}, {%4,%5,%6,%7}, {%8,%9}, {%0,%1,%2,%3};\n"
        : "+f"(c[0]), "+f"(c[1]), "+f"(c[2]), "+f"(c[3])
        : "r"(a[0]), "r"(a[1]), "r"(a[2]), "r"(a[3]), "r"(b[0]), "r"(b[1]));
}
__device__ __forceinline__ void cp16(uint32_t daddr, const void* gptr, int srcsize) {
    asm volatile("cp.async.ca.shared.global [%0], [%1], 16, %2;"
                 :: "r"(daddr), "l"(gptr), "r"(srcsize));
}
#define CP_COMMIT() asm volatile("cp.async.commit_group;" ::: "memory")
template <int NWAIT>
__device__ __forceinline__ void cp_wait() {
    asm volatile("cp.async.wait_group %0;" :: "n"(NWAIT) : "memory");
}
__device__ __forceinline__ uint32_t smem_u32(const void* p) {
    uint32_t a;
    asm("{ .reg .u64 t; cvta.to.shared.u64 t, %1; cvt.u32.u64 %0, t; }" : "=r"(a) : "l"(p));
    return a;
}

// ---------------- bf16-split tensor GEMM -------------------------------------
// C[n,M] = act(A[n,K] @ W[K,M] (+bias)); K%32==0. Tile 128x128xBK32, 8 warps 32x64.
// A, W given as split bf16 planes. Output: split bf16 (OUTSPLIT) or fp32.
// SMEM per stage: AH[128x40] AL BH[32x136] BL ; double-buffered.
static constexpr int SA = 40, SB = 136;
static constexpr int APL = 128 * SA * 2;           // 10240 B per A plane
static constexpr int BPL = 32 * SB * 2;            // 8704 B per B plane
static constexpr int STAGE = 2 * APL + 2 * BPL;    // 37888
static constexpr int GSMEM = 2 * STAGE;            // 75776

template <bool RELU, bool BIAS, bool OUTSPLIT>
__global__ __launch_bounds__(256, 1) void gemm_bs(
    const bf16* __restrict__ AH, const bf16* __restrict__ AL,
    const bf16* __restrict__ WH, const bf16* __restrict__ WL,
    const float* __restrict__ bias, float* __restrict__ Cf,
    bf16* __restrict__ CH, bf16* __restrict__ CL,
    int n, int K, int M)
{
    extern __shared__ char smem[];
    const uint32_t sbase = smem_u32(smem);
    const int tid = threadIdx.x, warp = tid >> 5, lane = tid & 31;
    const int wm = (warp & 3) * 32;
    const int wn = (warp >> 2) * 64;
    const int m0 = blockIdx.x * 128;
    const int n0 = blockIdx.y * 128;
    const int NC = K >> 5;

    float acc[2][8][4];
    #pragma unroll
    for (int i = 0; i < 2; i++)
        #pragma unroll
        for (int j = 0; j < 8; j++)
            #pragma unroll
            for (int q = 0; q < 4; q++) acc[i][j][q] = 0.f;

    // cp.async tile loader: chunk c -> stage b
    const int arow = tid >> 2, ach = tid & 3;       // A: 64 rows/pass, 4x16B chunks
    const int brow = tid >> 4, bch = tid & 15;      // B: 16 rows/pass, 16x16B chunks
    auto load_chunk = [&](int c, int b) {
        uint32_t st = sbase + b * STAGE;
        int k0 = c * 32;
        #pragma unroll
        for (int r = 0; r < 2; r++) {
            int rr = arow + r * 64;
            int g = m0 + rr;
            int sz = (g < n) ? 16 : 0;
            size_t go = (size_t)(g < n ? g : 0) * K + k0 + ach * 8;
            uint32_t da = st + rr * (SA * 2) + ach * 16;
            cp16(da,       AH + go, sz);
            cp16(da + APL, AL + go, sz);
        }
        #pragma unroll
        for (int r = 0; r < 2; r++) {
            int rr = brow + r * 16;
            int gm = n0 + bch * 8;
            int sz = (gm + 8 <= M) ? 16 : 0;
            size_t go = (size_t)(k0 + rr) * M + (gm + 8 <= M ? gm : 0);
            uint32_t db = st + 2 * APL + rr * (SB * 2) + bch * 16;
            cp16(db,       WH + go, sz);
            cp16(db + BPL, WL + go, sz);
        }
    };

    const int aLm = lane & 15, aLk = (lane >> 4) << 3;
    const int bLk = lane & 15, bLn = (lane >> 4) << 3;

    auto compute = [&](int b) {
        uint32_t pAH = sbase + b * STAGE;
        uint32_t pAL = pAH + APL;
        uint32_t pBH = pAH + 2 * APL;
        uint32_t pBL = pBH + BPL;
        #pragma unroll
        for (int ks = 0; ks < 32; ks += 16) {
            uint32_t afH[2][4], afL[2][4], bfH[4][4], bfL[4][4];
            #pragma unroll
            for (int mt = 0; mt < 2; mt++) {
                uint32_t off = (uint32_t)((wm + mt * 16 + aLm) * SA + ks + aLk) * 2;
                ldsm4(afH[mt], pAH + off);
                ldsm4(afL[mt], pAL + off);
            }
            #pragma unroll
            for (int ng = 0; ng < 4; ng++) {
                uint32_t off = (uint32_t)((ks + bLk) * SB + wn + ng * 16 + bLn) * 2;
                ldsm4t(bfH[ng], pBH + off);
                ldsm4t(bfL[ng], pBL + off);
            }
            #pragma unroll
            for (int mt = 0; mt < 2; mt++)
                #pragma unroll
                for (int nb = 0; nb < 8; nb++) {
                    const uint32_t* bh = &bfH[nb >> 1][(nb & 1) * 2];
                    const uint32_t* bl = &bfL[nb >> 1][(nb & 1) * 2];
                    mma16816(acc[mt][nb], afH[mt], bh);   // hi*hi
                    mma16816(acc[mt][nb], afH[mt], bl);   // hi*lo
                    mma16816(acc[mt][nb], afL[mt], bh);   // lo*hi
                }
        }
    };

    load_chunk(0, 0);
    CP_COMMIT();
    for (int c = 0; c < NC; c++) {
        if (c + 1 < NC) {
            load_chunk(c + 1, (c + 1) & 1);
            CP_COMMIT();
            cp_wait<1>();
        } else {
            cp_wait<0>();
        }
        __syncthreads();
        compute(c & 1);
        __syncthreads();
    }

    // epilogue: acc regs c0:(r,c) c1:(r,c+1) c2:(r+8,c) c3:(r+8,c+1)
    #pragma unroll
    for (int mt = 0; mt < 2; mt++)
        #pragma unroll
        for (int nb = 0; nb < 8; nb++) {
            int row = m0 + wm + mt * 16 + (lane >> 2);
            int col = n0 + wn + nb * 8 + (lane & 3) * 2;
            if (col >= M) continue;
            float v0 = acc[mt][nb][0], v1 = acc[mt][nb][1];
            float v2 = acc[mt][nb][2], v3 = acc[mt][nb][3];
            if (BIAS) {
                float b0 = bias[col], b1 = bias[col + 1];
                v0 += b0; v1 += b1; v2 += b0; v3 += b1;
            }
            if (RELU) {
                v0 = fmaxf(v0, 0.f); v1 = fmaxf(v1, 0.f);
                v2 = fmaxf(v2, 0.f); v3 = fmaxf(v3, 0.f);
            }
            if (OUTSPLIT) {
                uint32_t hu, lu;
                if (row < n) {
                    split_pair(v0, v1, hu, lu);
                    size_t oi = ((size_t)row * M + col) >> 1;
                    ((uint32_t*)CH)[oi] = hu;
                    ((uint32_t*)CL)[oi] = lu;
                }
                if (row + 8 < n) {
                    split_pair(v2, v3, hu, lu);
                    size_t oi = ((size_t)(row + 8) * M + col) >> 1;
                    ((uint32_t*)CH)[oi] = hu;
                    ((uint32_t*)CL)[oi] = lu;
                }
            } else {
                if (row < n)
                    *(float2*)(Cf + (size_t)row * M + col) = make_float2(v0, v1);
                if (row + 8 < n)
                    *(float2*)(Cf + (size_t)(row + 8) * M + col) = make_float2(v2, v3);
            }
        }
}

// ---------------- launch ----------------------------------------------------
extern "C" void kernel_launch(void* const* d_in, const int* in_sizes, int n_in,
                              void* d_out, int out_size) {
    const float* x    = (const float*)d_in[0];
    const int*   src  = (const int*)d_in[1];
    const int*   dst  = (const int*)d_in[2];
    const float* eps1 = (const float*)d_in[3];
    const float* w1a  = (const float*)d_in[4];
    const float* w1b  = (const float*)d_in[5];
    const float* eps2 = (const float*)d_in[6];
    const float* w2a  = (const float*)d_in[7];
    const float* w2b  = (const float*)d_in[8];
    const float* fcw  = (const float*)d_in[9];
    const float* fcb  = (const float*)d_in[10];
    float* out = (float*)d_out;

    const int n = in_sizes[0] / DD;   // 100000
    const int e = in_sizes[1];        // 1600000

    bf16 *aH, *aL, *tH, *tL, *hH, *hL, *wH, *wL;
    int *rs, *cur, *csr;
    cudaGetSymbolAddress((void**)&aH, g_aH); cudaGetSymbolAddress((void**)&aL, g_aL);
    cudaGetSymbolAddress((void**)&tH, g_tH); cudaGetSymbolAddress((void**)&tL, g_tL);
    cudaGetSymbolAddress((void**)&hH, g_hH); cudaGetSymbolAddress((void**)&hL, g_hL);
    cudaGetSymbolAddress((void**)&wH, g_wH); cudaGetSymbolAddress((void**)&wL, g_wL);
    cudaGetSymbolAddress((void**)&rs,  g_rowstart);
    cudaGetSymbolAddress((void**)&cur, g_cursor);
    cudaGetSymbolAddress((void**)&csr, g_csr);

    static bool attr_set = false;
    if (!attr_set) {
        cudaFuncSetAttribute(gemm_bs<true,  false, true >,
                             cudaFuncAttributeMaxDynamicSharedMemorySize, GSMEM);
        cudaFuncSetAttribute(gemm_bs<false, true,  false>,
                             cudaFuncAttributeMaxDynamicSharedMemorySize, GSMEM);
        attr_set = true;
    }

    // weight offsets in split weight buffer
    const int O1A = 0, O1B = 32768, O2A = 98304, O2B = 163840, OFC = 229376;

    // CSR build (dst-grouped)
    cudaMemsetAsync(cur, 0, (size_t)n * sizeof(int));
    int eb = (e + 255) / 256;
    hist_kernel<<<eb, 256>>>(dst, cur, e);
    scan_kernel<<<1, 1024>>>(cur, rs, n);
    fill_kernel<<<eb, 256>>>(src, dst, cur, csr, e);

    // weight splits (tiny)
    split_kernel<<<32,  256>>>(w1a, wH + O1A, wL + O1A, 32768);
    split_kernel<<<64,  256>>>(w1b, wH + O1B, wL + O1B, 65536);
    split_kernel<<<64,  256>>>(w2a, wH + O2A, wL + O2A, 65536);
    split_kernel<<<64,  256>>>(w2b, wH + O2B, wL + O2B, 65536);
    split_kernel<<<10,  256>>>(fcw, wH + OFC, wL + OFC, 10240);

    const int aggBlocks = (n + 7) / 8;
    const int gm = (n + 127) / 128;
    dim3 gFull(gm, HH / 128);   // (782, 2)
    dim3 gFc(gm, 1);

    // Layer 1
    agg_f32<<<aggBlocks, 256>>>((const float4*)x, rs, csr, eps1, aH, aL, n);
    gemm_bs<true, false, true><<<gFull, 256, GSMEM>>>(
        aH, aL, wH + O1A, wL + O1A, nullptr, nullptr, tH, tL, n, DD, HH);
    gemm_bs<true, false, true><<<gFull, 256, GSMEM>>>(
        tH, tL, wH + O1B, wL + O1B, nullptr, nullptr, hH, hL, n, HH, HH);
    // Layer 2
    agg_split<<<aggBlocks, 256>>>(hH, hL, rs, csr, eps2, aH, aL, n);
    gemm_bs<true, false, true><<<gFull, 256, GSMEM>>>(
        aH, aL, wH + O2A, wL + O2A, nullptr, nullptr, tH, tL, n, HH, HH);
    gemm_bs<true, false, true><<<gFull, 256, GSMEM>>>(
        tH, tL, wH + O2B, wL + O2B, nullptr, nullptr, hH, hL, n, HH, HH);
    // Classifier (fp32 out, bias, no relu)
    gemm_bs<false, true, false><<<gFc, 256, GSMEM>>>(
        hH, hL, wH + OFC, wL + OFC, fcb, out, nullptr, nullptr, n, HH, CC);
}

// round 8
// speedup vs baseline: 2.6595x; 1.6984x over previous
#include <cuda_runtime.h>
#include <cuda_fp16.h>
#include <cstdint>

// Problem constants: N=100000, E=1600000, D=128, H=256, C=40
#define NN 100000
#define EE 1600000
#define DD 128
#define HH 256
#define CC 40

// ---------------- scratch (static device globals) ---------------------------
// Activations: single fp16 plane. Weights: fp16 hi/lo planes (exact split).
__device__ __half g_aF[(size_t)NN * HH];   // rst (GEMM input)
__device__ __half g_tF[(size_t)NN * HH];   // mid
__device__ __half g_hF[(size_t)NN * HH];   // layer out
#define W_TOT (32768 + 65536 + 65536 + 65536 + 10240)
__device__ __half g_wH[W_TOT], g_wL[W_TOT];
__device__ int  g_rowstart[NN + 1];
__device__ int  g_cursor[NN];
__device__ int  g_csr[EE];

// ---------------- CSR build ------------------------------------------------
__global__ void hist_kernel(const int* __restrict__ dst, int* __restrict__ cnt, int e) {
    int i = blockIdx.x * blockDim.x + threadIdx.x;
    if (i < e) atomicAdd(&cnt[dst[i]], 1);
}

__global__ void scan_kernel(int* __restrict__ cnt_cursor, int* __restrict__ row_start, int n) {
    __shared__ int wsum[32];
    __shared__ int carry;
    const int tid = threadIdx.x;
    const int lane = tid & 31;
    const int wid = tid >> 5;
    if (tid == 0) carry = 0;
    __syncthreads();
    for (int base = 0; base < n; base += 1024) {
        int i = base + tid;
        int v = (i < n) ? cnt_cursor[i] : 0;
        int x = v;
        #pragma unroll
        for (int o = 1; o < 32; o <<= 1) {
            int y = __shfl_up_sync(0xffffffffu, x, o);
            if (lane >= o) x += y;
        }
        if (lane == 31) wsum[wid] = x;
        __syncthreads();
        if (wid == 0) {
            int wv = wsum[lane];
            #pragma unroll
            for (int o = 1; o < 32; o <<= 1) {
                int y = __shfl_up_sync(0xffffffffu, wv, o);
                if (lane >= o) wv += y;
            }
            wsum[lane] = wv;
        }
        __syncthreads();
        int excl = x - v + (wid ? wsum[wid - 1] : 0) + carry;
        if (i < n) { row_start[i] = excl; cnt_cursor[i] = excl; }
        if (i == n - 1) row_start[n] = excl + v;
        __syncthreads();
        if (tid == 0) carry += wsum[31];
        __syncthreads();
    }
}

__global__ void fill_kernel(const int* __restrict__ src, const int* __restrict__ dst,
                            int* __restrict__ cursor, int* __restrict__ csr, int e) {
    int i = blockIdx.x * blockDim.x + threadIdx.x;
    if (i < e) {
        int p = atomicAdd(&cursor[dst[i]], 1);
        csr[p] = src[i];
    }
}

// ---------------- fp16 helpers ----------------------------------------------
__device__ __forceinline__ uint32_t packh(__half a, __half b) {
    __half2 h = __halves2half2(a, b);
    return *(uint32_t*)&h;
}
__device__ __forceinline__ float2 unpk_h2(uint32_t u) {
    __half2 h = *(__half2*)&u;
    return __half22float2(h);
}
// exact hi/lo split of fp32 into two fp16 (weights)
__device__ __forceinline__ void wsplit_pair(float v0, float v1, uint32_t& hu, uint32_t& lu) {
    __half h0 = __float2half_rn(v0), h1 = __float2half_rn(v1);
    __half l0 = __float2half_rn(v0 - __half2float(h0));
    __half l1 = __float2half_rn(v1 - __half2float(h1));
    hu = packh(h0, h1); lu = packh(l0, l1);
}

// Weight splitter: count % 4 == 0
__global__ void split_kernel(const float* __restrict__ src, __half* __restrict__ dh,
                             __half* __restrict__ dl, int cnt) {
    int i = blockIdx.x * blockDim.x + threadIdx.x;
    if (i * 4 < cnt) {
        float4 v = ((const float4*)src)[i];
        uint2 hi, lo;
        wsplit_pair(v.x, v.y, hi.x, lo.x);
        wsplit_pair(v.z, v.w, hi.y, lo.y);
        ((uint2*)dh)[i] = hi;
        ((uint2*)dl)[i] = lo;
    }
}

// ---------------- aggregation (gather, warp/node) ---------------------------
// agg1: fp32 input (x, D=128) -> fp16 output
__global__ __launch_bounds__(256) void agg_f32(
    const float4* __restrict__ h, const int* __restrict__ rs,
    const int* __restrict__ csr, const float* __restrict__ eps,
    __half* __restrict__ oF, int n)
{
    int w = (blockIdx.x * 256 + threadIdx.x) >> 5;
    if (w >= n) return;
    int lane = threadIdx.x & 31;
    float s = 1.0f + *eps;
    float4 v = h[(size_t)w * 32 + lane];
    float a0 = v.x * s, a1 = v.y * s, a2 = v.z * s, a3 = v.w * s;
    int e0 = rs[w], e1 = rs[w + 1];
    for (int e = e0; e < e1; e++) {
        float4 u = h[(size_t)csr[e] * 32 + lane];
        a0 += u.x; a1 += u.y; a2 += u.z; a3 += u.w;
    }
    uint2 o;
    o.x = packh(__float2half_rn(a0), __float2half_rn(a1));
    o.y = packh(__float2half_rn(a2), __float2half_rn(a3));
    *(uint2*)((uint32_t*)oF + (size_t)w * 64 + lane * 2) = o;
}

// agg2: fp16 input (D=256) -> fp16 output; 512B gather per edge
__global__ __launch_bounds__(256) void agg_h(
    const __half* __restrict__ iF, const int* __restrict__ rs,
    const int* __restrict__ csr, const float* __restrict__ eps,
    __half* __restrict__ oF, int n)
{
    int w = (blockIdx.x * 256 + threadIdx.x) >> 5;
    if (w >= n) return;
    int lane = threadIdx.x & 31;
    float s = 1.0f + *eps;
    float acc[8];
    {
        uint4 hv = ((const uint4*)(iF + (size_t)w * 256))[lane];
        const uint32_t* hp = (const uint32_t*)&hv;
        #pragma unroll
        for (int j = 0; j < 4; j++) {
            float2 f = unpk_h2(hp[j]);
            acc[2 * j]     = f.x * s;
            acc[2 * j + 1] = f.y * s;
        }
    }
    int e0 = rs[w], e1 = rs[w + 1];
    for (int e = e0; e < e1; e++) {
        uint4 hv = ((const uint4*)(iF + (size_t)csr[e] * 256))[lane];
        const uint32_t* hp = (const uint32_t*)&hv;
        #pragma unroll
        for (int j = 0; j < 4; j++) {
            float2 f = unpk_h2(hp[j]);
            acc[2 * j]     += f.x;
            acc[2 * j + 1] += f.y;
        }
    }
    uint4 o;
    o.x = packh(__float2half_rn(acc[0]), __float2half_rn(acc[1]));
    o.y = packh(__float2half_rn(acc[2]), __float2half_rn(acc[3]));
    o.z = packh(__float2half_rn(acc[4]), __float2half_rn(acc[5]));
    o.w = packh(__float2half_rn(acc[6]), __float2half_rn(acc[7]));
    *(uint4*)((uint32_t*)oF + (size_t)w * 128 + lane * 4) = o;
}

// ---------------- mma.sync helpers ------------------------------------------
__device__ __forceinline__ void ldsm4(uint32_t* r, uint32_t addr) {
    asm volatile("ldmatrix.sync.aligned.m8n8.x4.shared.b16 {%0,%1,%2,%3}, [%4];\n"
        : "=r"(r[0]), "=r"(r[1]), "=r"(r[2]), "=r"(r[3]) : "r"(addr));
}
__device__ __forceinline__ void ldsm4t(uint32_t* r, uint32_t addr) {
    asm volatile("ldmatrix.sync.aligned.m8n8.x4.trans.shared.b16 {%0,%1,%2,%3}, [%4];\n"
        : "=r"(r[0]), "=r"(r[1]), "=r"(r[2]), "=r"(r[3]) : "r"(addr));
}
__device__ __forceinline__ void mma16816(float* c, const uint32_t* a, const uint32_t* b) {
    asm volatile("mma.sync.aligned.m16n8k16.row.col.f32.f16.f16.f32 "
        "{%0,%1,%2,%3}, {%4,%5,%6,%7}, {%8,%9}, {%0,%1,%2,%3};\n"
        : "+f"(c[0]), "+f"(c[1]), "+f"(c[2]), "+f"(c[3])
        : "r"(a[0]), "r"(a[1]), "r"(a[2]), "r"(a[3]), "r"(b[0]), "r"(b[1]));
}
__device__ __forceinline__ void cp16(uint32_t daddr, const void* gptr, int srcsize) {
    asm volatile("cp.async.ca.shared.global [%0], [%1], 16, %2;"
                 :: "r"(daddr), "l"(gptr), "r"(srcsize));
}
#define CP_COMMIT() asm volatile("cp.async.commit_group;" ::: "memory")
template <int NWAIT>
__device__ __forceinline__ void cp_wait() {
    asm volatile("cp.async.wait_group %0;" :: "n"(NWAIT) : "memory");
}
__device__ __forceinline__ uint32_t smem_u32(const void* p) {
    uint32_t a;
    asm("{ .reg .u64 t; cvta.to.shared.u64 t, %1; cvt.u32.u64 %0, t; }" : "=r"(a) : "l"(p));
    return a;
}

// ---------------- fp16 asymmetric-split tensor GEMM --------------------------
// C[n,M] = act(A_f16[n,K] @ (W_hi+W_lo)[K,M] (+bias)); K%32==0.
// Tile 128x128xBK32, 8 warps (32x64 each), 2 mma products per fragment pair.
static constexpr int SA = 40, SB = 136;
static constexpr int APL = 128 * SA * 2;           // 10240 B  (A: 1 plane)
static constexpr int BPL = 32 * SB * 2;            // 8704  B  per W plane
static constexpr int STAGE = APL + 2 * BPL;        // 27648
static constexpr int GSMEM = 2 * STAGE;            // 55296 -> 2 CTAs/SM

template <bool RELU, bool BIAS, bool OUTHALF>
__global__ __launch_bounds__(256, 2) void gemm_hs(
    const __half* __restrict__ A,
    const __half* __restrict__ WH, const __half* __restrict__ WL,
    const float* __restrict__ bias, float* __restrict__ Cf,
    __half* __restrict__ Ch,
    int n, int K, int M)
{
    extern __shared__ char smem[];
    const uint32_t sbase = smem_u32(smem);
    const int tid = threadIdx.x, warp = tid >> 5, lane = tid & 31;
    const int wm = (warp & 3) * 32;
    const int wn = (warp >> 2) * 64;
    const int m0 = blockIdx.x * 128;
    const int n0 = blockIdx.y * 128;
    const int NC = K >> 5;

    float acc[2][8][4];
    #pragma unroll
    for (int i = 0; i < 2; i++)
        #pragma unroll
        for (int j = 0; j < 8; j++)
            #pragma unroll
            for (int q = 0; q < 4; q++) acc[i][j][q] = 0.f;

    // cp.async tile loader: chunk c -> stage b
    const int arow = tid >> 2, ach = tid & 3;       // A: 64 rows/pass, 4x16B
    const int brow = tid >> 4, bch = tid & 15;      // B: 16 rows/pass, 16x16B
    auto load_chunk = [&](int c, int b) {
        uint32_t st = sbase + b * STAGE;
        int k0 = c * 32;
        #pragma unroll
        for (int r = 0; r < 2; r++) {
            int rr = arow + r * 64;
            int g = m0 + rr;
            int sz = (g < n) ? 16 : 0;
            size_t go = (size_t)(g < n ? g : 0) * K + k0 + ach * 8;
            cp16(st + rr * (SA * 2) + ach * 16, A + go, sz);
        }
        #pragma unroll
        for (int r = 0; r < 2; r++) {
            int rr = brow + r * 16;
            int gm = n0 + bch * 8;
            int sz = (gm + 8 <= M) ? 16 : 0;
            size_t go = (size_t)(k0 + rr) * M + (gm + 8 <= M ? gm : 0);
            uint32_t db = st + APL + rr * (SB * 2) + bch * 16;
            cp16(db,       WH + go, sz);
            cp16(db + BPL, WL + go, sz);
        }
    };

    const int aLm = lane & 15, aLk = (lane >> 4) << 3;
    const int bLk = lane & 15, bLn = (lane >> 4) << 3;

    auto compute = [&](int b) {
        uint32_t pA  = sbase + b * STAGE;
        uint32_t pBH = pA + APL;
        uint32_t pBL = pBH + BPL;
        #pragma unroll
        for (int ks = 0; ks < 32; ks += 16) {
            uint32_t af[2][4];
            #pragma unroll
            for (int mt = 0; mt < 2; mt++) {
                uint32_t off = (uint32_t)((wm + mt * 16 + aLm) * SA + ks + aLk) * 2;
                ldsm4(af[mt], pA + off);
            }
            // per n-group: load hi/lo B frags (8 regs live), 8 mma
            #pragma unroll
            for (int ng = 0; ng < 4; ng++) {
                uint32_t bfH[4], bfL[4];
                uint32_t off = (uint32_t)((ks + bLk) * SB + wn + ng * 16 + bLn) * 2;
                ldsm4t(bfH, pBH + off);
                ldsm4t(bfL, pBL + off);
                #pragma unroll
                for (int half_ = 0; half_ < 2; half_++) {
                    int nb = ng * 2 + half_;
                    #pragma unroll
                    for (int mt = 0; mt < 2; mt++) {
                        mma16816(acc[mt][nb], af[mt], &bfH[half_ * 2]);
                        mma16816(acc[mt][nb], af[mt], &bfL[half_ * 2]);
                    }
                }
            }
        }
    };

    load_chunk(0, 0);
    CP_COMMIT();
    for (int c = 0; c < NC; c++) {
        if (c + 1 < NC) {
            load_chunk(c + 1, (c + 1) & 1);
            CP_COMMIT();
            cp_wait<1>();
        } else {
            cp_wait<0>();
        }
        __syncthreads();
        compute(c & 1);
        __syncthreads();
    }

    // epilogue: c0:(r,c) c1:(r,c+1) c2:(r+8,c) c3:(r+8,c+1)
    #pragma unroll
    for (int mt = 0; mt < 2; mt++)
        #pragma unroll
        for (int nb = 0; nb < 8; nb++) {
            int row = m0 + wm + mt * 16 + (lane >> 2);
            int col = n0 + wn + nb * 8 + (lane & 3) * 2;
            if (col >= M) continue;
            float v0 = acc[mt][nb][0], v1 = acc[mt][nb][1];
            float v2 = acc[mt][nb][2], v3 = acc[mt][nb][3];
            if (BIAS) {
                float b0 = bias[col], b1 = bias[col + 1];
                v0 += b0; v1 += b1; v2 += b0; v3 += b1;
            }
            if (RELU) {
                v0 = fmaxf(v0, 0.f); v1 = fmaxf(v1, 0.f);
                v2 = fmaxf(v2, 0.f); v3 = fmaxf(v3, 0.f);
            }
            if (OUTHALF) {
                if (row < n)
                    ((uint32_t*)Ch)[((size_t)row * M + col) >> 1] =
                        packh(__float2half_rn(v0), __float2half_rn(v1));
                if (row + 8 < n)
                    ((uint32_t*)Ch)[((size_t)(row + 8) * M + col) >> 1] =
                        packh(__float2half_rn(v2), __float2half_rn(v3));
            } else {
                if (row < n)
                    *(float2*)(Cf + (size_t)row * M + col) = make_float2(v0, v1);
                if (row + 8 < n)
                    *(float2*)(Cf + (size_t)(row + 8) * M + col) = make_float2(v2, v3);
            }
        }
}

// ---------------- launch ----------------------------------------------------
extern "C" void kernel_launch(void* const* d_in, const int* in_sizes, int n_in,
                              void* d_out, int out_size) {
    const float* x    = (const float*)d_in[0];
    const int*   src  = (const int*)d_in[1];
    const int*   dst  = (const int*)d_in[2];
    const float* eps1 = (const float*)d_in[3];
    const float* w1a  = (const float*)d_in[4];
    const float* w1b  = (const float*)d_in[5];
    const float* eps2 = (const float*)d_in[6];
    const float* w2a  = (const float*)d_in[7];
    const float* w2b  = (const float*)d_in[8];
    const float* fcw  = (const float*)d_in[9];
    const float* fcb  = (const float*)d_in[10];
    float* out = (float*)d_out;

    const int n = in_sizes[0] / DD;   // 100000
    const int e = in_sizes[1];        // 1600000

    __half *aF, *tF, *hF, *wH, *wL;
    int *rs, *cur, *csr;
    cudaGetSymbolAddress((void**)&aF, g_aF);
    cudaGetSymbolAddress((void**)&tF, g_tF);
    cudaGetSymbolAddress((void**)&hF, g_hF);
    cudaGetSymbolAddress((void**)&wH, g_wH);
    cudaGetSymbolAddress((void**)&wL, g_wL);
    cudaGetSymbolAddress((void**)&rs,  g_rowstart);
    cudaGetSymbolAddress((void**)&cur, g_cursor);
    cudaGetSymbolAddress((void**)&csr, g_csr);

    static bool attr_set = false;
    if (!attr_set) {
        cudaFuncSetAttribute(gemm_hs<true,  false, true >,
                             cudaFuncAttributeMaxDynamicSharedMemorySize, GSMEM);
        cudaFuncSetAttribute(gemm_hs<false, true,  false>,
                             cudaFuncAttributeMaxDynamicSharedMemorySize, GSMEM);
        attr_set = true;
    }

    // weight offsets in split weight buffer
    const int O1A = 0, O1B = 32768, O2A = 98304, O2B = 163840, OFC = 229376;

    // CSR build (dst-grouped)
    cudaMemsetAsync(cur, 0, (size_t)n * sizeof(int));
    int eb = (e + 255) / 256;
    hist_kernel<<<eb, 256>>>(dst, cur, e);
    scan_kernel<<<1, 1024>>>(cur, rs, n);
    fill_kernel<<<eb, 256>>>(src, dst, cur, csr, e);

    // weight splits (tiny)
    split_kernel<<<32,  256>>>(w1a, wH + O1A, wL + O1A, 32768);
    split_kernel<<<64,  256>>>(w1b, wH + O1B, wL + O1B, 65536);
    split_kernel<<<64,  256>>>(w2a, wH + O2A, wL + O2A, 65536);
    split_kernel<<<64,  256>>>(w2b, wH + O2B, wL + O2B, 65536);
    split_kernel<<<10,  256>>>(fcw, wH + OFC, wL + OFC, 10240);

    const int aggBlocks = (n + 7) / 8;
    const int gm = (n + 127) / 128;
    dim3 gFull(gm, HH / 128);   // (782, 2)
    dim3 gFc(gm, 1);

    // Layer 1
    agg_f32<<<aggBlocks, 256>>>((const float4*)x, rs, csr, eps1, aF, n);
    gemm_hs<true, false, true><<<gFull, 256, GSMEM>>>(
        aF, wH + O1A, wL + O1A, nullptr, nullptr, tF, n, DD, HH);
    gemm_hs<true, false, true><<<gFull, 256, GSMEM>>>(
        tF, wH + O1B, wL + O1B, nullptr, nullptr, hF, n, HH, HH);
    // Layer 2
    agg_h<<<aggBlocks, 256>>>(hF, rs, csr, eps2, aF, n);
    gemm_hs<true, false, true><<<gFull, 256, GSMEM>>>(
        aF, wH + O2A, wL + O2A, nullptr, nullptr, tF, n, HH, HH);
    gemm_hs<true, false, true><<<gFull, 256, GSMEM>>>(
        tF, wH + O2B, wL + O2B, nullptr, nullptr, hF, n, HH, HH);
    // Classifier (fp32 out, bias, no relu)
    gemm_hs<false, true, false><<<gFc, 256, GSMEM>>>(
        hF, wH + OFC, wL + OFC, fcb, out, nullptr, n, HH, CC);
}

// round 9
// speedup vs baseline: 2.8307x; 1.0644x over previous
#include <cuda_runtime.h>
#include <cuda_fp16.h>
#include <cstdint>

// Problem constants: N=100000, E=1600000, D=128, H=256, C=40
#define NN 100000
#define EE 1600000
#define DD 128
#define HH 256
#define CC 40

// ---------------- scratch (static device globals) ---------------------------
__device__ __half g_aF[(size_t)NN * HH];   // rst (GEMM input)
__device__ __half g_tF[(size_t)NN * HH];   // mid / x-fp16 staging
__device__ __half g_hF[(size_t)NN * HH];   // layer out
#define W_TOT (32768 + 65536 + 65536 + 65536 + 10240)
__device__ __half g_wH[W_TOT], g_wL[W_TOT];
__device__ int  g_rowstart[NN + 1];
__device__ int  g_cursor[NN];
__device__ int  g_csr[EE];

// ---------------- CSR build ------------------------------------------------
__global__ void hist_kernel(const int* __restrict__ dst, int* __restrict__ cnt, int e) {
    int i = blockIdx.x * blockDim.x + threadIdx.x;
    if (i < e) atomicAdd(&cnt[dst[i]], 1);
}

__global__ void scan_kernel(int* __restrict__ cnt_cursor, int* __restrict__ row_start, int n) {
    __shared__ int wsum[32];
    __shared__ int carry;
    const int tid = threadIdx.x;
    const int lane = tid & 31;
    const int wid = tid >> 5;
    if (tid == 0) carry = 0;
    __syncthreads();
    for (int base = 0; base < n; base += 1024) {
        int i = base + tid;
        int v = (i < n) ? cnt_cursor[i] : 0;
        int x = v;
        #pragma unroll
        for (int o = 1; o < 32; o <<= 1) {
            int y = __shfl_up_sync(0xffffffffu, x, o);
            if (lane >= o) x += y;
        }
        if (lane == 31) wsum[wid] = x;
        __syncthreads();
        if (wid == 0) {
            int wv = wsum[lane];
            #pragma unroll
            for (int o = 1; o < 32; o <<= 1) {
                int y = __shfl_up_sync(0xffffffffu, wv, o);
                if (lane >= o) wv += y;
            }
            wsum[lane] = wv;
        }
        __syncthreads();
        int excl = x - v + (wid ? wsum[wid - 1] : 0) + carry;
        if (i < n) { row_start[i] = excl; cnt_cursor[i] = excl; }
        if (i == n - 1) row_start[n] = excl + v;
        __syncthreads();
        if (tid == 0) carry += wsum[31];
        __syncthreads();
    }
}

__global__ void fill_kernel(const int* __restrict__ src, const int* __restrict__ dst,
                            int* __restrict__ cursor, int* __restrict__ csr, int e) {
    int i = blockIdx.x * blockDim.x + threadIdx.x;
    if (i < e) {
        int p = atomicAdd(&cursor[dst[i]], 1);
        csr[p] = src[i];
    }
}

// ---------------- fp16 helpers ----------------------------------------------
__device__ __forceinline__ uint32_t packh(__half a, __half b) {
    __half2 h = __halves2half2(a, b);
    return *(uint32_t*)&h;
}
__device__ __forceinline__ float2 unpk_h2(uint32_t u) {
    __half2 h = *(__half2*)&u;
    return __half22float2(h);
}
__device__ __forceinline__ void wsplit_pair(float v0, float v1, uint32_t& hu, uint32_t& lu) {
    __half h0 = __float2half_rn(v0), h1 = __float2half_rn(v1);
    __half l0 = __float2half_rn(v0 - __half2float(h0));
    __half l1 = __float2half_rn(v1 - __half2float(h1));
    hu = packh(h0, h1); lu = packh(l0, l1);
}

// Merged weight splitter: all 5 matrices in one launch.
__global__ void split_all_kernel(
    const float* __restrict__ w1a, const float* __restrict__ w1b,
    const float* __restrict__ w2a, const float* __restrict__ w2b,
    const float* __restrict__ fcw,
    __half* __restrict__ dh, __half* __restrict__ dl)
{
    int i = blockIdx.x * blockDim.x + threadIdx.x;   // vec4 index
    int i4 = i * 4;
    if (i4 >= W_TOT) return;
    const float* s; int off;
    if      (i4 < 32768)  { s = w1a; off = i4; }
    else if (i4 < 98304)  { s = w1b; off = i4 - 32768; }
    else if (i4 < 163840) { s = w2a; off = i4 - 98304; }
    else if (i4 < 229376) { s = w2b; off = i4 - 163840; }
    else                  { s = fcw; off = i4 - 229376; }
    float4 v = *(const float4*)(s + off);
    uint2 hi, lo;
    wsplit_pair(v.x, v.y, hi.x, lo.x);
    wsplit_pair(v.z, v.w, hi.y, lo.y);
    ((uint2*)dh)[i] = hi;
    ((uint2*)dl)[i] = lo;
}

// fp32 -> fp16 bulk convert (cnt4 = float4 count)
__global__ void f2h_kernel(const float4* __restrict__ src, __half* __restrict__ dst, int cnt4) {
    int i = blockIdx.x * blockDim.x + threadIdx.x;
    if (i < cnt4) {
        float4 v = src[i];
        uint2 o;
        o.x = packh(__float2half_rn(v.x), __float2half_rn(v.y));
        o.y = packh(__float2half_rn(v.z), __float2half_rn(v.w));
        ((uint2*)dst)[i] = o;
    }
}

// ---------------- aggregation (gather, warp/node, fp16 I/O) ------------------
// D=128: 256B per edge gather (uint2 per lane)
__global__ __launch_bounds__(256) void agg_h128(
    const __half* __restrict__ iF, const int* __restrict__ rs,
    const int* __restrict__ csr, const float* __restrict__ eps,
    __half* __restrict__ oF, int n)
{
    int w = (blockIdx.x * 256 + threadIdx.x) >> 5;
    if (w >= n) return;
    int lane = threadIdx.x & 31;
    float s = 1.0f + *eps;
    float acc[4];
    {
        uint2 u = ((const uint2*)(iF + (size_t)w * 128))[lane];
        float2 f0 = unpk_h2(u.x), f1 = unpk_h2(u.y);
        acc[0] = f0.x * s; acc[1] = f0.y * s; acc[2] = f1.x * s; acc[3] = f1.y * s;
    }
    int e0 = rs[w], e1 = rs[w + 1];
    for (int e = e0; e < e1; e++) {
        uint2 u = ((const uint2*)(iF + (size_t)csr[e] * 128))[lane];
        float2 f0 = unpk_h2(u.x), f1 = unpk_h2(u.y);
        acc[0] += f0.x; acc[1] += f0.y; acc[2] += f1.x; acc[3] += f1.y;
    }
    uint2 o;
    o.x = packh(__float2half_rn(acc[0]), __float2half_rn(acc[1]));
    o.y = packh(__float2half_rn(acc[2]), __float2half_rn(acc[3]));
    *(uint2*)((uint32_t*)oF + (size_t)w * 64 + lane * 2) = o;
}

// D=256: 512B per edge gather (uint4 per lane)
__global__ __launch_bounds__(256) void agg_h256(
    const __half* __restrict__ iF, const int* __restrict__ rs,
    const int* __restrict__ csr, const float* __restrict__ eps,
    __half* __restrict__ oF, int n)
{
    int w = (blockIdx.x * 256 + threadIdx.x) >> 5;
    if (w >= n) return;
    int lane = threadIdx.x & 31;
    float s = 1.0f + *eps;
    float acc[8];
    {
        uint4 hv = ((const uint4*)(iF + (size_t)w * 256))[lane];
        const uint32_t* hp = (const uint32_t*)&hv;
        #pragma unroll
        for (int j = 0; j < 4; j++) {
            float2 f = unpk_h2(hp[j]);
            acc[2 * j] = f.x * s; acc[2 * j + 1] = f.y * s;
        }
    }
    int e0 = rs[w], e1 = rs[w + 1];
    for (int e = e0; e < e1; e++) {
        uint4 hv = ((const uint4*)(iF + (size_t)csr[e] * 256))[lane];
        const uint32_t* hp = (const uint32_t*)&hv;
        #pragma unroll
        for (int j = 0; j < 4; j++) {
            float2 f = unpk_h2(hp[j]);
            acc[2 * j] += f.x; acc[2 * j + 1] += f.y;
        }
    }
    uint4 o;
    o.x = packh(__float2half_rn(acc[0]), __float2half_rn(acc[1]));
    o.y = packh(__float2half_rn(acc[2]), __float2half_rn(acc[3]));
    o.z = packh(__float2half_rn(acc[4]), __float2half_rn(acc[5]));
    o.w = packh(__float2half_rn(acc[6]), __float2half_rn(acc[7]));
    *(uint4*)((uint32_t*)oF + (size_t)w * 128 + lane * 4) = o;
}

// ---------------- mma.sync helpers ------------------------------------------
__device__ __forceinline__ void ldsm4(uint32_t* r, uint32_t addr) {
    asm volatile("ldmatrix.sync.aligned.m8n8.x4.shared.b16 {%0,%1,%2,%3}, [%4];\n"
        : "=r"(r[0]), "=r"(r[1]), "=r"(r[2]), "=r"(r[3]) : "r"(addr));
}
__device__ __forceinline__ void ldsm4t(uint32_t* r, uint32_t addr) {
    asm volatile("ldmatrix.sync.aligned.m8n8.x4.trans.shared.b16 {%0,%1,%2,%3}, [%4];\n"
        : "=r"(r[0]), "=r"(r[1]), "=r"(r[2]), "=r"(r[3]) : "r"(addr));
}
__device__ __forceinline__ void mma16816(float* c, const uint32_t* a, const uint32_t* b) {
    asm volatile("mma.sync.aligned.m16n8k16.row.col.f32.f16.f16.f32 "
        "{%0,%1,%2,%3}, {%4,%5,%6,%7}, {%8,%9}, {%0,%1,%2,%3};\n"
        : "+f"(c[0]), "+f"(c[1]), "+f"(c[2]), "+f"(c[3])
        : "r"(a[0]), "r"(a[1]), "r"(a[2]), "r"(a[3]), "r"(b[0]), "r"(b[1]));
}
__device__ __forceinline__ void cp16(uint32_t daddr, const void* gptr, int srcsize) {
    asm volatile("cp.async.ca.shared.global [%0], [%1], 16, %2;"
                 :: "r"(daddr), "l"(gptr), "r"(srcsize));
}
#define CP_COMMIT() asm volatile("cp.async.commit_group;" ::: "memory")
template <int NWAIT>
__device__ __forceinline__ void cp_wait() {
    asm volatile("cp.async.wait_group %0;" :: "n"(NWAIT) : "memory");
}
__device__ __forceinline__ uint32_t smem_u32(const void* p) {
    uint32_t a;
    asm("{ .reg .u64 t; cvta.to.shared.u64 t, %1; cvt.u32.u64 %0, t; }" : "=r"(a) : "l"(p));
    return a;
}

// ---------------- fp16 asymmetric-split tensor GEMM --------------------------
// C[n,M] = act(A_f16[n,K] @ (W_hi+W_lo)[K,M] (+bias)); K%32==0.
// CTA tile 128 x BN (BN = NWCOL*32), 8 warps: (8/NWCOL) m-rows x NWCOL n-cols.
// Warp tile: (128/(8/NWCOL)) x 32. Double-buffered cp.async, BK=32.
template <int NWCOL, bool RELU, bool BIAS, bool OUTHALF>
__global__ __launch_bounds__(256, 2) void gemm_hs(
    const __half* __restrict__ A,
    const __half* __restrict__ WH, const __half* __restrict__ WL,
    const float* __restrict__ bias, float* __restrict__ Cf,
    __half* __restrict__ Ch,
    int n, int K, int M)
{
    constexpr int BN    = NWCOL * 32;
    constexpr int MROWS = 8 / NWCOL;          // warp rows (2 or 4)
    constexpr int WTM   = 128 / MROWS;        // warp tile m (64 or 32)
    constexpr int MT    = WTM / 16;           // m16 tiles per warp (4 or 2)
    constexpr int SA    = 40;
    constexpr int SB    = BN + 8;
    constexpr int APL   = 128 * SA * 2;
    constexpr int BPL   = 32 * SB * 2;
    constexpr int STAGE = APL + 2 * BPL;
    constexpr int BCH   = BN / 8;             // cp16 per B row
    constexpr int BRPP  = 256 / BCH;          // B rows per pass
    constexpr int BPASS = 32 / BRPP;          // passes

    extern __shared__ char smem[];
    const uint32_t sbase = smem_u32(smem);
    const int tid = threadIdx.x, warp = tid >> 5, lane = tid & 31;
    const int wm = (warp % MROWS) * WTM;
    const int wn = (warp / MROWS) * 32;
    const int m0 = blockIdx.x * 128;
    const int n0 = blockIdx.y * BN;
    const int NC = K >> 5;

    float acc[MT][4][4];
    #pragma unroll
    for (int i = 0; i < MT; i++)
        #pragma unroll
        for (int j = 0; j < 4; j++)
            #pragma unroll
            for (int q = 0; q < 4; q++) acc[i][j][q] = 0.f;

    const int arow = tid >> 2, ach = tid & 3;
    const int brow = tid / BCH, bch = tid % BCH;
    auto load_chunk = [&](int c, int b) {
        uint32_t st = sbase + b * STAGE;
        int k0 = c * 32;
        #pragma unroll
        for (int r = 0; r < 2; r++) {
            int rr = arow + r * 64;
            int g = m0 + rr;
            int sz = (g < n) ? 16 : 0;
            size_t go = (size_t)(g < n ? g : 0) * K + k0 + ach * 8;
            cp16(st + rr * (SA * 2) + ach * 16, A + go, sz);
        }
        #pragma unroll
        for (int r = 0; r < BPASS; r++) {
            int rr = brow + r * BRPP;
            int gm = n0 + bch * 8;
            int sz = (gm + 8 <= M) ? 16 : 0;
            size_t go = (size_t)(k0 + rr) * M + (gm + 8 <= M ? gm : 0);
            uint32_t db = st + APL + rr * (SB * 2) + bch * 16;
            cp16(db,       WH + go, sz);
            cp16(db + BPL, WL + go, sz);
        }
    };

    const int aLm = lane & 15, aLk = (lane >> 4) << 3;
    const int bLk = lane & 15, bLn = (lane >> 4) << 3;

    auto compute = [&](int b) {
        uint32_t pA  = sbase + b * STAGE;
        uint32_t pBH = pA + APL;
        uint32_t pBL = pBH + BPL;
        #pragma unroll
        for (int ks = 0; ks < 32; ks += 16) {
            uint32_t af[MT][4];
            #pragma unroll
            for (int mt = 0; mt < MT; mt++) {
                uint32_t off = (uint32_t)((wm + mt * 16 + aLm) * SA + ks + aLk) * 2;
                ldsm4(af[mt], pA + off);
            }
            #pragma unroll
            for (int ng = 0; ng < 2; ng++) {
                uint32_t bfH[4], bfL[4];
                uint32_t off = (uint32_t)((ks + bLk) * SB + wn + ng * 16 + bLn) * 2;
                ldsm4t(bfH, pBH + off);
                ldsm4t(bfL, pBL + off);
                #pragma unroll
                for (int half_ = 0; half_ < 2; half_++) {
                    int nb = ng * 2 + half_;
                    #pragma unroll
                    for (int mt = 0; mt < MT; mt++) {
                        mma16816(acc[mt][nb], af[mt], &bfH[half_ * 2]);
                        mma16816(acc[mt][nb], af[mt], &bfL[half_ * 2]);
                    }
                }
            }
        }
    };

    load_chunk(0, 0);
    CP_COMMIT();
    for (int c = 0; c < NC; c++) {
        if (c + 1 < NC) {
            load_chunk(c + 1, (c + 1) & 1);
            CP_COMMIT();
            cp_wait<1>();
        } else {
            cp_wait<0>();
        }
        __syncthreads();
        compute(c & 1);
        __syncthreads();
    }

    // epilogue: c0:(r,c) c1:(r,c+1) c2:(r+8,c) c3:(r+8,c+1)
    #pragma unroll
    for (int mt = 0; mt < MT; mt++)
        #pragma unroll
        for (int nb = 0; nb < 4; nb++) {
            int row = m0 + wm + mt * 16 + (lane >> 2);
            int col = n0 + wn + nb * 8 + (lane & 3) * 2;
            if (col >= M) continue;
            float v0 = acc[mt][nb][0], v1 = acc[mt][nb][1];
            float v2 = acc[mt][nb][2], v3 = acc[mt][nb][3];
            if (BIAS) {
                float b0 = bias[col], b1 = bias[col + 1];
                v0 += b0; v1 += b1; v2 += b0; v3 += b1;
            }
            if (RELU) {
                v0 = fmaxf(v0, 0.f); v1 = fmaxf(v1, 0.f);
                v2 = fmaxf(v2, 0.f); v3 = fmaxf(v3, 0.f);
            }
            if (OUTHALF) {
                if (row < n)
                    ((uint32_t*)Ch)[((size_t)row * M + col) >> 1] =
                        packh(__float2half_rn(v0), __float2half_rn(v1));
                if (row + 8 < n)
                    ((uint32_t*)Ch)[((size_t)(row + 8) * M + col) >> 1] =
                        packh(__float2half_rn(v2), __float2half_rn(v3));
            } else {
                if (row < n)
                    *(float2*)(Cf + (size_t)row * M + col) = make_float2(v0, v1);
                if (row + 8 < n)
                    *(float2*)(Cf + (size_t)(row + 8) * M + col) = make_float2(v2, v3);
            }
        }
}

static constexpr int GSMEM4 = 2 * (128 * 40 * 2 + 2 * (32 * 136 * 2));  // 55296
static constexpr int GSMEM2 = 2 * (128 * 40 * 2 + 2 * (32 * 72 * 2));   // 38912

// ---------------- launch ----------------------------------------------------
extern "C" void kernel_launch(void* const* d_in, const int* in_sizes, int n_in,
                              void* d_out, int out_size) {
    const float* x    = (const float*)d_in[0];
    const int*   src  = (const int*)d_in[1];
    const int*   dst  = (const int*)d_in[2];
    const float* eps1 = (const float*)d_in[3];
    const float* w1a  = (const float*)d_in[4];
    const float* w1b  = (const float*)d_in[5];
    const float* eps2 = (const float*)d_in[6];
    const float* w2a  = (const float*)d_in[7];
    const float* w2b  = (const float*)d_in[8];
    const float* fcw  = (const float*)d_in[9];
    const float* fcb  = (const float*)d_in[10];
    float* out = (float*)d_out;

    const int n = in_sizes[0] / DD;   // 100000
    const int e = in_sizes[1];        // 1600000

    __half *aF, *tF, *hF, *wH, *wL;
    int *rs, *cur, *csr;
    cudaGetSymbolAddress((void**)&aF, g_aF);
    cudaGetSymbolAddress((void**)&tF, g_tF);
    cudaGetSymbolAddress((void**)&hF, g_hF);
    cudaGetSymbolAddress((void**)&wH, g_wH);
    cudaGetSymbolAddress((void**)&wL, g_wL);
    cudaGetSymbolAddress((void**)&rs,  g_rowstart);
    cudaGetSymbolAddress((void**)&cur, g_cursor);
    cudaGetSymbolAddress((void**)&csr, g_csr);

    cudaFuncSetAttribute(gemm_hs<4, true,  false, true >,
                         cudaFuncAttributeMaxDynamicSharedMemorySize, GSMEM4);
    cudaFuncSetAttribute(gemm_hs<2, false, true,  false>,
                         cudaFuncAttributeMaxDynamicSharedMemorySize, GSMEM2);

    // weight offsets in split weight buffer
    const int O1A = 0, O1B = 32768, O2A = 98304, O2B = 163840, OFC = 229376;

    // CSR build (dst-grouped)
    cudaMemsetAsync(cur, 0, (size_t)n * sizeof(int));
    int eb = (e + 255) / 256;
    hist_kernel<<<eb, 256>>>(dst, cur, e);
    scan_kernel<<<1, 1024>>>(cur, rs, n);
    fill_kernel<<<eb, 256>>>(src, dst, cur, csr, e);

    // one-shot conversions
    split_all_kernel<<<(W_TOT / 4 + 255) / 256, 256>>>(w1a, w1b, w2a, w2b, fcw, wH, wL);
    f2h_kernel<<<(n * DD / 4 + 255) / 256, 256>>>((const float4*)x, tF, n * DD / 4);

    const int aggBlocks = (n + 7) / 8;
    const int gm = (n + 127) / 128;
    dim3 gFull(gm, HH / 128);   // (782, 2)
    dim3 gFc(gm, 1);

    // Layer 1  (x-fp16 staged in tF; consumed by agg before G1 overwrites tF)
    agg_h128<<<aggBlocks, 256>>>(tF, rs, csr, eps1, aF, n);
    gemm_hs<4, true, false, true><<<gFull, 256, GSMEM4>>>(
        aF, wH + O1A, wL + O1A, nullptr, nullptr, tF, n, DD, HH);
    gemm_hs<4, true, false, true><<<gFull, 256, GSMEM4>>>(
        tF, wH + O1B, wL + O1B, nullptr, nullptr, hF, n, HH, HH);
    // Layer 2
    agg_h256<<<aggBlocks, 256>>>(hF, rs, csr, eps2, aF, n);
    gemm_hs<4, true, false, true><<<gFull, 256, GSMEM4>>>(
        aF, wH + O2A, wL + O2A, nullptr, nullptr, tF, n, HH, HH);
    gemm_hs<4, true, false, true><<<gFull, 256, GSMEM4>>>(
        tF, wH + O2B, wL + O2B, nullptr, nullptr, hF, n, HH, HH);
    // Classifier (BN=64 tile, fp32 out, bias, no relu)
    gemm_hs<2, false, true, false><<<gFc, 256, GSMEM2>>>(
        hF, wH + OFC, wL + OFC, fcb, out, nullptr, n, HH, CC);
}

// round 10
// speedup vs baseline: 2.8398x; 1.0032x over previous
#include <cuda_runtime.h>
#include <cuda_fp16.h>
#include <cstdint>

// Problem constants: N=100000, E=1600000, D=128, H=256, C=40
#define NN 100000
#define EE 1600000
#define DD 128
#define HH 256
#define CC 40

// ---------------- scratch (static device globals) ---------------------------
__device__ __half g_aF[(size_t)NN * HH];   // rst (GEMM input)
__device__ __half g_tF[(size_t)NN * HH];   // mid / x-fp16 staging
__device__ __half g_hF[(size_t)NN * HH];   // layer out
#define W_TOT (32768 + 65536 + 65536 + 65536 + 10240)
__device__ __half g_wH[W_TOT], g_wL[W_TOT];
__device__ int  g_rowstart[NN + 1];
__device__ int  g_cursor[NN];
__device__ int  g_csr[EE];

// ---------------- CSR build ------------------------------------------------
__global__ void hist_kernel(const int* __restrict__ dst, int* __restrict__ cnt, int e) {
    int i = blockIdx.x * blockDim.x + threadIdx.x;
    if (i < e) atomicAdd(&cnt[dst[i]], 1);
}

__global__ void scan_kernel(int* __restrict__ cnt_cursor, int* __restrict__ row_start, int n) {
    __shared__ int wsum[32];
    __shared__ int carry;
    const int tid = threadIdx.x;
    const int lane = tid & 31;
    const int wid = tid >> 5;
    if (tid == 0) carry = 0;
    __syncthreads();
    for (int base = 0; base < n; base += 1024) {
        int i = base + tid;
        int v = (i < n) ? cnt_cursor[i] : 0;
        int x = v;
        #pragma unroll
        for (int o = 1; o < 32; o <<= 1) {
            int y = __shfl_up_sync(0xffffffffu, x, o);
            if (lane >= o) x += y;
        }
        if (lane == 31) wsum[wid] = x;
        __syncthreads();
        if (wid == 0) {
            int wv = wsum[lane];
            #pragma unroll
            for (int o = 1; o < 32; o <<= 1) {
                int y = __shfl_up_sync(0xffffffffu, wv, o);
                if (lane >= o) wv += y;
            }
            wsum[lane] = wv;
        }
        __syncthreads();
        int excl = x - v + (wid ? wsum[wid - 1] : 0) + carry;
        if (i < n) { row_start[i] = excl; cnt_cursor[i] = excl; }
        if (i == n - 1) row_start[n] = excl + v;
        __syncthreads();
        if (tid == 0) carry += wsum[31];
        __syncthreads();
    }
}

__global__ void fill_kernel(const int* __restrict__ src, const int* __restrict__ dst,
                            int* __restrict__ cursor, int* __restrict__ csr, int e) {
    int i = blockIdx.x * blockDim.x + threadIdx.x;
    if (i < e) {
        int p = atomicAdd(&cursor[dst[i]], 1);
        csr[p] = src[i];
    }
}

// ---------------- fp16 helpers ----------------------------------------------
__device__ __forceinline__ uint32_t packh(__half a, __half b) {
    __half2 h = __halves2half2(a, b);
    return *(uint32_t*)&h;
}
__device__ __forceinline__ float2 unpk_h2(uint32_t u) {
    __half2 h = *(__half2*)&u;
    return __half22float2(h);
}
__device__ __forceinline__ void wsplit_pair(float v0, float v1, uint32_t& hu, uint32_t& lu) {
    __half h0 = __float2half_rn(v0), h1 = __float2half_rn(v1);
    __half l0 = __float2half_rn(v0 - __half2float(h0));
    __half l1 = __float2half_rn(v1 - __half2float(h1));
    hu = packh(h0, h1); lu = packh(l0, l1);
}

// Merged weight splitter: all 5 matrices in one launch.
__global__ void split_all_kernel(
    const float* __restrict__ w1a, const float* __restrict__ w1b,
    const float* __restrict__ w2a, const float* __restrict__ w2b,
    const float* __restrict__ fcw,
    __half* __restrict__ dh, __half* __restrict__ dl)
{
    int i = blockIdx.x * blockDim.x + threadIdx.x;   // vec4 index
    int i4 = i * 4;
    if (i4 >= W_TOT) return;
    const float* s; int off;
    if      (i4 < 32768)  { s = w1a; off = i4; }
    else if (i4 < 98304)  { s = w1b; off = i4 - 32768; }
    else if (i4 < 163840) { s = w2a; off = i4 - 98304; }
    else if (i4 < 229376) { s = w2b; off = i4 - 163840; }
    else                  { s = fcw; off = i4 - 229376; }
    float4 v = *(const float4*)(s + off);
    uint2 hi, lo;
    wsplit_pair(v.x, v.y, hi.x, lo.x);
    wsplit_pair(v.z, v.w, hi.y, lo.y);
    ((uint2*)dh)[i] = hi;
    ((uint2*)dl)[i] = lo;
}

// fp32 -> fp16 bulk convert (cnt4 = float4 count)
__global__ void f2h_kernel(const float4* __restrict__ src, __half* __restrict__ dst, int cnt4) {
    int i = blockIdx.x * blockDim.x + threadIdx.x;
    if (i < cnt4) {
        float4 v = src[i];
        uint2 o;
        o.x = packh(__float2half_rn(v.x), __float2half_rn(v.y));
        o.y = packh(__float2half_rn(v.z), __float2half_rn(v.w));
        ((uint2*)dst)[i] = o;
    }
}

// ---------------- aggregation (gather, warp/node, fp16 I/O) ------------------
// D=128: 256B per edge gather (uint2 per lane)
__global__ __launch_bounds__(256) void agg_h128(
    const __half* __restrict__ iF, const int* __restrict__ rs,
    const int* __restrict__ csr, const float* __restrict__ eps,
    __half* __restrict__ oF, int n)
{
    int w = (blockIdx.x * 256 + threadIdx.x) >> 5;
    if (w >= n) return;
    int lane = threadIdx.x & 31;
    float s = 1.0f + *eps;
    float acc[4];
    {
        uint2 u = ((const uint2*)(iF + (size_t)w * 128))[lane];
        float2 f0 = unpk_h2(u.x), f1 = unpk_h2(u.y);
        acc[0] = f0.x * s; acc[1] = f0.y * s; acc[2] = f1.x * s; acc[3] = f1.y * s;
    }
    int e0 = rs[w], e1 = rs[w + 1];
    for (int e = e0; e < e1; e++) {
        uint2 u = ((const uint2*)(iF + (size_t)csr[e] * 128))[lane];
        float2 f0 = unpk_h2(u.x), f1 = unpk_h2(u.y);
        acc[0] += f0.x; acc[1] += f0.y; acc[2] += f1.x; acc[3] += f1.y;
    }
    uint2 o;
    o.x = packh(__float2half_rn(acc[0]), __float2half_rn(acc[1]));
    o.y = packh(__float2half_rn(acc[2]), __float2half_rn(acc[3]));
    *(uint2*)((uint32_t*)oF + (size_t)w * 64 + lane * 2) = o;
}

// D=256: 512B per edge gather (uint4 per lane)
__global__ __launch_bounds__(256) void agg_h256(
    const __half* __restrict__ iF, const int* __restrict__ rs,
    const int* __restrict__ csr, const float* __restrict__ eps,
    __half* __restrict__ oF, int n)
{
    int w = (blockIdx.x * 256 + threadIdx.x) >> 5;
    if (w >= n) return;
    int lane = threadIdx.x & 31;
    float s = 1.0f + *eps;
    float acc[8];
    {
        uint4 hv = ((const uint4*)(iF + (size_t)w * 256))[lane];
        const uint32_t* hp = (const uint32_t*)&hv;
        #pragma unroll
        for (int j = 0; j < 4; j++) {
            float2 f = unpk_h2(hp[j]);
            acc[2 * j] = f.x * s; acc[2 * j + 1] = f.y * s;
        }
    }
    int e0 = rs[w], e1 = rs[w + 1];
    for (int e = e0; e < e1; e++) {
        uint4 hv = ((const uint4*)(iF + (size_t)csr[e] * 256))[lane];
        const uint32_t* hp = (const uint32_t*)&hv;
        #pragma unroll
        for (int j = 0; j < 4; j++) {
            float2 f = unpk_h2(hp[j]);
            acc[2 * j] += f.x; acc[2 * j + 1] += f.y;
        }
    }
    uint4 o;
    o.x = packh(__float2half_rn(acc[0]), __float2half_rn(acc[1]));
    o.y = packh(__float2half_rn(acc[2]), __float2half_rn(acc[3]));
    o.z = packh(__float2half_rn(acc[4]), __float2half_rn(acc[5]));
    o.w = packh(__float2half_rn(acc[6]), __float2half_rn(acc[7]));
    *(uint4*)((uint32_t*)oF + (size_t)w * 128 + lane * 4) = o;
}

// ---------------- mma.sync helpers ------------------------------------------
__device__ __forceinline__ void ldsm4(uint32_t* r, uint32_t addr) {
    asm volatile("ldmatrix.sync.aligned.m8n8.x4.shared.b16 {%0,%1,%2,%3}, [%4];\n"
        : "=r"(r[0]), "=r"(r[1]), "=r"(r[2]), "=r"(r[3]) : "r"(addr));
}
__device__ __forceinline__ void ldsm4t(uint32_t* r, uint32_t addr) {
    asm volatile("ldmatrix.sync.aligned.m8n8.x4.trans.shared.b16 {%0,%1,%2,%3}, [%4];\n"
        : "=r"(r[0]), "=r"(r[1]), "=r"(r[2]), "=r"(r[3]) : "r"(addr));
}
__device__ __forceinline__ void mma16816(float* c, const uint32_t* a, const uint32_t* b) {
    asm volatile("mma.sync.aligned.m16n8k16.row.col.f32.f16.f16.f32 "
        "{%0,%1,%2,%3}, {%4,%5,%6,%7}, {%8,%9}, {%0,%1,%2,%3};\n"
        : "+f"(c[0]), "+f"(c[1]), "+f"(c[2]), "+f"(c[3])
        : "r"(a[0]), "r"(a[1]), "r"(a[2]), "r"(a[3]), "r"(b[0]), "r"(b[1]));
}
__device__ __forceinline__ void cp16(uint32_t daddr, const void* gptr, int srcsize) {
    asm volatile("cp.async.ca.shared.global [%0], [%1], 16, %2;"
                 :: "r"(daddr), "l"(gptr), "r"(srcsize));
}
#define CP_COMMIT() asm volatile("cp.async.commit_group;" ::: "memory")
template <int NWAIT>
__device__ __forceinline__ void cp_wait() {
    asm volatile("cp.async.wait_group %0;" :: "n"(NWAIT) : "memory");
}
__device__ __forceinline__ uint32_t smem_u32(const void* p) {
    uint32_t a;
    asm("{ .reg .u64 t; cvta.to.shared.u64 t, %1; cvt.u32.u64 %0, t; }" : "=r"(a) : "l"(p));
    return a;
}

// ---------------- fp16 asymmetric-split tensor GEMM --------------------------
// C[n,M] = act(A_f16[n,K] @ (W_hi+W_lo)[K,M] (+bias)); K%32==0.
// CTA tile 128 x BN (BN = NWCOL*32), 8 warps: (8/NWCOL) m-rows x NWCOL n-cols.
// 3-stage cp.async ring, ONE __syncthreads per K-chunk:
//   wait<1> -> sync -> issue load chunk c+2 (always commit) -> compute(c)
// The single barrier both publishes chunk c and proves all warps finished
// chunk c-1, whose slot ((c+2)%3 == (c-1)%3) is the one being refilled.
template <int NWCOL, bool RELU, bool BIAS, bool OUTHALF>
__global__ __launch_bounds__(256, 2) void gemm_hs(
    const __half* __restrict__ A,
    const __half* __restrict__ WH, const __half* __restrict__ WL,
    const float* __restrict__ bias, float* __restrict__ Cf,
    __half* __restrict__ Ch,
    int n, int K, int M)
{
    constexpr int BN    = NWCOL * 32;
    constexpr int MROWS = 8 / NWCOL;          // warp rows (2 or 4)
    constexpr int WTM   = 128 / MROWS;        // warp tile m (64 or 32)
    constexpr int MT    = WTM / 16;           // m16 tiles per warp (4 or 2)
    constexpr int SA    = 40;
    constexpr int SB    = BN + 8;
    constexpr int APL   = 128 * SA * 2;
    constexpr int BPL   = 32 * SB * 2;
    constexpr int STAGE = APL + 2 * BPL;
    constexpr int BCH   = BN / 8;             // cp16 per B row
    constexpr int BRPP  = 256 / BCH;          // B rows per pass
    constexpr int BPASS = 32 / BRPP;          // passes

    extern __shared__ char smem[];
    const uint32_t sbase = smem_u32(smem);
    const int tid = threadIdx.x, warp = tid >> 5, lane = tid & 31;
    const int wm = (warp % MROWS) * WTM;
    const int wn = (warp / MROWS) * 32;
    const int m0 = blockIdx.x * 128;
    const int n0 = blockIdx.y * BN;
    const int NC = K >> 5;

    float acc[MT][4][4];
    #pragma unroll
    for (int i = 0; i < MT; i++)
        #pragma unroll
        for (int j = 0; j < 4; j++)
            #pragma unroll
            for (int q = 0; q < 4; q++) acc[i][j][q] = 0.f;

    const int arow = tid >> 2, ach = tid & 3;
    const int brow = tid / BCH, bch = tid % BCH;
    auto load_chunk = [&](int c, int b) {
        uint32_t st = sbase + b * STAGE;
        int k0 = c * 32;
        #pragma unroll
        for (int r = 0; r < 2; r++) {
            int rr = arow + r * 64;
            int g = m0 + rr;
            int sz = (g < n) ? 16 : 0;
            size_t go = (size_t)(g < n ? g : 0) * K + k0 + ach * 8;
            cp16(st + rr * (SA * 2) + ach * 16, A + go, sz);
        }
        #pragma unroll
        for (int r = 0; r < BPASS; r++) {
            int rr = brow + r * BRPP;
            int gm = n0 + bch * 8;
            int sz = (gm + 8 <= M) ? 16 : 0;
            size_t go = (size_t)(k0 + rr) * M + (gm + 8 <= M ? gm : 0);
            uint32_t db = st + APL + rr * (SB * 2) + bch * 16;
            cp16(db,       WH + go, sz);
            cp16(db + BPL, WL + go, sz);
        }
    };

    const int aLm = lane & 15, aLk = (lane >> 4) << 3;
    const int bLk = lane & 15, bLn = (lane >> 4) << 3;

    auto compute = [&](int b) {
        uint32_t pA  = sbase + b * STAGE;
        uint32_t pBH = pA + APL;
        uint32_t pBL = pBH + BPL;
        #pragma unroll
        for (int ks = 0; ks < 32; ks += 16) {
            uint32_t af[MT][4];
            #pragma unroll
            for (int mt = 0; mt < MT; mt++) {
                uint32_t off = (uint32_t)((wm + mt * 16 + aLm) * SA + ks + aLk) * 2;
                ldsm4(af[mt], pA + off);
            }
            #pragma unroll
            for (int ng = 0; ng < 2; ng++) {
                uint32_t bfH[4], bfL[4];
                uint32_t off = (uint32_t)((ks + bLk) * SB + wn + ng * 16 + bLn) * 2;
                ldsm4t(bfH, pBH + off);
                ldsm4t(bfL, pBL + off);
                #pragma unroll
                for (int half_ = 0; half_ < 2; half_++) {
                    int nb = ng * 2 + half_;
                    #pragma unroll
                    for (int mt = 0; mt < MT; mt++) {
                        mma16816(acc[mt][nb], af[mt], &bfH[half_ * 2]);
                        mma16816(acc[mt][nb], af[mt], &bfL[half_ * 2]);
                    }
                }
            }
        }
    };

    // 3-stage pipeline
    load_chunk(0, 0); CP_COMMIT();
    load_chunk(1, 1); CP_COMMIT();
    for (int c = 0; c < NC; c++) {
        cp_wait<1>();            // chunk c complete (newest group may be in flight)
        __syncthreads();         // publish chunk c; all warps done with chunk c-1
        if (c + 2 < NC) load_chunk(c + 2, (c + 2) % 3);
        CP_COMMIT();             // always commit (empty groups keep count aligned)
        compute(c % 3);
    }

    // epilogue: c0:(r,c) c1:(r,c+1) c2:(r+8,c) c3:(r+8,c+1)
    #pragma unroll
    for (int mt = 0; mt < MT; mt++)
        #pragma unroll
        for (int nb = 0; nb < 4; nb++) {
            int row = m0 + wm + mt * 16 + (lane >> 2);
            int col = n0 + wn + nb * 8 + (lane & 3) * 2;
            if (col >= M) continue;
            float v0 = acc[mt][nb][0], v1 = acc[mt][nb][1];
            float v2 = acc[mt][nb][2], v3 = acc[mt][nb][3];
            if (BIAS) {
                float b0 = bias[col], b1 = bias[col + 1];
                v0 += b0; v1 += b1; v2 += b0; v3 += b1;
            }
            if (RELU) {
                v0 = fmaxf(v0, 0.f); v1 = fmaxf(v1, 0.f);
                v2 = fmaxf(v2, 0.f); v3 = fmaxf(v3, 0.f);
            }
            if (OUTHALF) {
                if (row < n)
                    ((uint32_t*)Ch)[((size_t)row * M + col) >> 1] =
                        packh(__float2half_rn(v0), __float2half_rn(v1));
                if (row + 8 < n)
                    ((uint32_t*)Ch)[((size_t)(row + 8) * M + col) >> 1] =
                        packh(__float2half_rn(v2), __float2half_rn(v3));
            } else {
                if (row < n)
                    *(float2*)(Cf + (size_t)row * M + col) = make_float2(v0, v1);
                if (row + 8 < n)
                    *(float2*)(Cf + (size_t)(row + 8) * M + col) = make_float2(v2, v3);
            }
        }
}

static constexpr int GSMEM4 = 3 * (128 * 40 * 2 + 2 * (32 * 136 * 2));  // 82944
static constexpr int GSMEM2 = 3 * (128 * 40 * 2 + 2 * (32 * 72 * 2));   // 58368

// ---------------- launch ----------------------------------------------------
extern "C" void kernel_launch(void* const* d_in, const int* in_sizes, int n_in,
                              void* d_out, int out_size) {
    const float* x    = (const float*)d_in[0];
    const int*   src  = (const int*)d_in[1];
    const int*   dst  = (const int*)d_in[2];
    const float* eps1 = (const float*)d_in[3];
    const float* w1a  = (const float*)d_in[4];
    const float* w1b  = (const float*)d_in[5];
    const float* eps2 = (const float*)d_in[6];
    const float* w2a  = (const float*)d_in[7];
    const float* w2b  = (const float*)d_in[8];
    const float* fcw  = (const float*)d_in[9];
    const float* fcb  = (const float*)d_in[10];
    float* out = (float*)d_out;

    const int n = in_sizes[0] / DD;   // 100000
    const int e = in_sizes[1];        // 1600000

    __half *aF, *tF, *hF, *wH, *wL;
    int *rs, *cur, *csr;
    cudaGetSymbolAddress((void**)&aF, g_aF);
    cudaGetSymbolAddress((void**)&tF, g_tF);
    cudaGetSymbolAddress((void**)&hF, g_hF);
    cudaGetSymbolAddress((void**)&wH, g_wH);
    cudaGetSymbolAddress((void**)&wL, g_wL);
    cudaGetSymbolAddress((void**)&rs,  g_rowstart);
    cudaGetSymbolAddress((void**)&cur, g_cursor);
    cudaGetSymbolAddress((void**)&csr, g_csr);

    cudaFuncSetAttribute(gemm_hs<4, true,  false, true >,
                         cudaFuncAttributeMaxDynamicSharedMemorySize, GSMEM4);
    cudaFuncSetAttribute(gemm_hs<2, false, true,  false>,
                         cudaFuncAttributeMaxDynamicSharedMemorySize, GSMEM2);

    // weight offsets in split weight buffer
    const int O1A = 0, O1B = 32768, O2A = 98304, O2B = 163840, OFC = 229376;

    // CSR build (dst-grouped)
    cudaMemsetAsync(cur, 0, (size_t)n * sizeof(int));
    int eb = (e + 255) / 256;
    hist_kernel<<<eb, 256>>>(dst, cur, e);
    scan_kernel<<<1, 1024>>>(cur, rs, n);
    fill_kernel<<<eb, 256>>>(src, dst, cur, csr, e);

    // one-shot conversions
    split_all_kernel<<<(W_TOT / 4 + 255) / 256, 256>>>(w1a, w1b, w2a, w2b, fcw, wH, wL);
    f2h_kernel<<<(n * DD / 4 + 255) / 256, 256>>>((const float4*)x, tF, n * DD / 4);

    const int aggBlocks = (n + 7) / 8;
    const int gm = (n + 127) / 128;
    dim3 gFull(gm, HH / 128);   // (782, 2)
    dim3 gFc(gm, 1);

    // Layer 1  (x-fp16 staged in tF; consumed by agg before G1 overwrites tF)
    agg_h128<<<aggBlocks, 256>>>(tF, rs, csr, eps1, aF, n);
    gemm_hs<4, true, false, true><<<gFull, 256, GSMEM4>>>(
        aF, wH + O1A, wL + O1A, nullptr, nullptr, tF, n, DD, HH);
    gemm_hs<4, true, false, true><<<gFull, 256, GSMEM4>>>(
        tF, wH + O1B, wL + O1B, nullptr, nullptr, hF, n, HH, HH);
    // Layer 2
    agg_h256<<<aggBlocks, 256>>>(hF, rs, csr, eps2, aF, n);
    gemm_hs<4, true, false, true><<<gFull, 256, GSMEM4>>>(
        aF, wH + O2A, wL + O2A, nullptr, nullptr, tF, n, HH, HH);
    gemm_hs<4, true, false, true><<<gFull, 256, GSMEM4>>>(
        tF, wH + O2B, wL + O2B, nullptr, nullptr, hF, n, HH, HH);
    // Classifier (BN=64 tile, fp32 out, bias, no relu)
    gemm_hs<2, false, true, false><<<gFc, 256, GSMEM2>>>(
        hF, wH + OFC, wL + OFC, fcb, out, nullptr, n, HH, CC);
}